// round 6
// baseline (speedup 1.0000x reference)
#include <cuda_runtime.h>

#define T_STEPS 512
#define BATCH   256
#define WG      128
#define NSTAGES 144     // q: s1 0..15, s2 16..79, s3 80..143

// Ping-pong activation buffers, layout [t][feature(16)][batch]
__device__ __align__(16) float g_act[2][T_STEPS * 16 * BATCH];
// Flags [stage][split(4)][t]; cleared by pre_kernel each replay.
__device__ unsigned g_flags[NSTAGES * 4 * T_STEPS];

#define FLAG(q, s) (g_flags + ((size_t)(q) * 4 + (s)) * T_STEPS)

// ---------------------------------------------------------------------------
__device__ __forceinline__ unsigned ld_acq(const unsigned* p) {
    unsigned v;
    asm volatile("ld.acquire.gpu.global.u32 %0, [%1];" : "=r"(v) : "l"(p) : "memory");
    return v;
}
__device__ __forceinline__ void st_rel(unsigned* p, unsigned v) {
    asm volatile("st.release.gpu.global.u32 [%0], %1;" :: "l"(p), "r"(v) : "memory");
}
__device__ __forceinline__ float2 ffma2(float2 a, float2 b, float2 c) {
    float2 d;
    asm("fma.rn.f32x2 %0, %1, %2, %3;"
        : "=l"(reinterpret_cast<unsigned long long&>(d))
        : "l"(reinterpret_cast<unsigned long long&>(a)),
          "l"(reinterpret_cast<unsigned long long&>(b)),
          "l"(reinterpret_cast<unsigned long long&>(c)));
    return d;
}
__device__ __forceinline__ void wg_bar(int id) {
    asm volatile("bar.sync %0, %1;" :: "r"(id), "r"(WG) : "memory");
}

// Exact LSTM nonlinearity, shared-denominator form: 5 ex2 + 2 rcp.
__device__ __forceinline__ float cell_one(float gi, float gf, float gg, float go,
                                          float& c) {
    gi = fminf(fmaxf(gi, -15.f), 15.f);
    gf = fminf(fmaxf(gf, -15.f), 15.f);
    gg = fminf(fmaxf(gg, -15.f), 15.f);
    go = fminf(fmaxf(go, -15.f), 15.f);
    float a  = __expf(-gi);
    float fe = __expf(-gf);
    float b  = __expf(-2.f * gg);
    float na = 1.f + a, nf = 1.f + fe, nb = 1.f + b;
    float num = fmaf(c * na, nb, (1.f - b) * nf);
    c = __fdividef(num, nf * na * nb);
    float ct = fminf(fmaxf(c, -15.f), 15.f);
    float d  = __expf(-2.f * ct);
    float oe = __expf(-go);
    return __fdividef(1.f - d, (1.f + oe) * (1.f + d));
}

// ---------------------------------------------------------------------------
// Scalar weight fill: W[g][k], k<din from Wih, [din,H) zero, [H,2H) from Whh.
// ---------------------------------------------------------------------------
template<int H, int DIN0>
__device__ void fill_s(float* W, float* B,
                       const float* Wih0, const float* Whh0,
                       const float* bih0, const float* bhh0,
                       const float* Wih,  const float* Whh,
                       const float* bih,  const float* bhh,
                       int l, int wtid, int stride) {
    constexpr int G = 4 * H, KM = 2 * H;
    const float* wi = l ? Wih + (size_t)(l - 1) * G * H : Wih0;
    const float* wh = l ? Whh + (size_t)(l - 1) * G * H : Whh0;
    const float* bi = l ? bih + (l - 1) * G : bih0;
    const float* bh = l ? bhh + (l - 1) * G : bhh0;
    const int din = l ? H : DIN0;
    for (int i = wtid; i < G * KM; i += stride) {
        int g = i / KM, k = i % KM;
        float w = 0.f;
        if (k < din)     w = wi[g * din + k];
        else if (k >= H) w = wh[g * H + (k - H)];
        W[i] = w;
    }
    for (int i = wtid; i < G; i += stride) B[i] = bi[i] + bh[i];
}

// ---------------------------------------------------------------------------
// Warpgroup stage loop with register-prefetched input staging.
// rows: [0,H) staged input (rows [DSTAGE,H) stay zero), layer p h at
// [(p+1)H,(p+2)H).  2 barriers/step for PACK=1.
// ---------------------------------------------------------------------------
template<int H, int PACK, int BPC_, int DSTAGE, bool FIRST, bool RELU, bool LAST>
__device__ void stage_loop(const float* __restrict__ sW, const float* __restrict__ sB,
                           float2* rows,
                           const float* __restrict__ bufin, float* __restrict__ bufout,
                           const unsigned* fin, unsigned* fout, int b0,
                           int wtid, int barid) {
    constexpr int GROUPS = WG / H;
    constexpr int NB = BPC_ / GROUPS;
    constexpr int KM = 2 * H;
    constexpr int QROW = BPC_ / 2;           // float4 slots per row
    constexpr int NQ = DSTAGE * QROW;
    constexpr int NLD = NQ / WG;             // all configs divide exactly
    const int j = wtid / GROUPS, group = wtid % GROUPS;

    float2 c[PACK][NB];
#pragma unroll
    for (int p = 0; p < PACK; p++)
#pragma unroll
        for (int n = 0; n < NB; n++) c[p][n] = make_float2(0.f, 0.f);

    float4 pf[NLD];
    // Prologue: fetch input for t=0
    if (!FIRST) { const unsigned* f = fin; while (ld_acq(f) == 0) { } }
    {
        const float* bin = bufin + b0;
#pragma unroll
        for (int L = 0; L < NLD; L++) {
            int i = wtid + L * WG;
            int m = i / QROW, q4 = i % QROW;
            pf[L] = __ldcg(reinterpret_cast<const float4*>(&bin[m * BATCH + 4 * q4]));
        }
    }

    for (int t = 0; t < T_STEPS; t++) {
        // Phase A: commit staged input regs to smem
#pragma unroll
        for (int L = 0; L < NLD; L++) {
            int i = wtid + L * WG;
            int m = i / QROW, q4 = i % QROW;
            float4 v = pf[L];
            if (RELU) {
                v.x = fmaxf(v.x, 0.f); v.y = fmaxf(v.y, 0.f);
                v.z = fmaxf(v.z, 0.f); v.w = fmaxf(v.w, 0.f);
            }
            *reinterpret_cast<float4*>(&rows[m * BPC_ + 2 * q4]) = v;
        }
        wg_bar(barid);     // input(t) + h(t-1) visible

        // Prefetch input t+1 (overlaps FMA below)
        if (t + 1 < T_STEPS) {
            if (!FIRST) { const unsigned* f = fin + t + 1; while (ld_acq(f) == 0) { } }
            const float* bin = bufin + (size_t)(t + 1) * 16 * BATCH + b0;
#pragma unroll
            for (int L = 0; L < NLD; L++) {
                int i = wtid + L * WG;
                int m = i / QROW, q4 = i % QROW;
                pf[L] = __ldcg(reinterpret_cast<const float4*>(&bin[m * BATCH + 4 * q4]));
            }
        }

        float* bout = bufout + (size_t)t * 16 * BATCH + b0;
#pragma unroll
        for (int p = 0; p < PACK; p++) {
            const float* W = sW + p * 4 * H * KM;
            const float* B = sB + p * 4 * H;
            const float2* vin = rows + p * H * BPC_;

            float2 acc[4][NB];
#pragma unroll
            for (int q = 0; q < 4; q++) {
                float bv = B[q * H + j];
#pragma unroll
                for (int n = 0; n < NB; n++) acc[q][n] = make_float2(bv, bv);
            }
#pragma unroll 4
            for (int k = 0; k < KM; k++) {
                float s0 = W[(0 * H + j) * KM + k];
                float s1 = W[(1 * H + j) * KM + k];
                float s2 = W[(2 * H + j) * KM + k];
                float s3 = W[(3 * H + j) * KM + k];
                float2 w0 = make_float2(s0, s0), w1 = make_float2(s1, s1);
                float2 w2 = make_float2(s2, s2), w3 = make_float2(s3, s3);
#pragma unroll
                for (int n = 0; n < NB; n++) {
                    float2 v = vin[k * BPC_ + n * GROUPS + group];
                    acc[0][n] = ffma2(w0, v, acc[0][n]);
                    acc[1][n] = ffma2(w1, v, acc[1][n]);
                    acc[2][n] = ffma2(w2, v, acc[2][n]);
                    acc[3][n] = ffma2(w3, v, acc[3][n]);
                }
            }
            float2 h2[NB];
#pragma unroll
            for (int n = 0; n < NB; n++) {
                h2[n].x = cell_one(acc[0][n].x, acc[1][n].x, acc[2][n].x,
                                   acc[3][n].x, c[p][n].x);
                h2[n].y = cell_one(acc[0][n].y, acc[1][n].y, acc[2][n].y,
                                   acc[3][n].y, c[p][n].y);
            }
            if (p == PACK - 1) {
#pragma unroll
                for (int n = 0; n < NB; n++) {
                    int bp = n * GROUPS + group;
                    *reinterpret_cast<float2*>(&bout[j * BATCH + 2 * bp]) = h2[n];
                }
            }
            wg_bar(barid);     // all smem reads of this pack done; gout issued
            float2* hrow = rows + (p + 1) * H * BPC_ + j * BPC_;
#pragma unroll
            for (int n = 0; n < NB; n++) hrow[n * GROUPS + group] = h2[n];
            if (p < PACK - 1) wg_bar(barid);
            // last pack: h writes covered by next iteration's phase-A barrier
        }
        if (!LAST && wtid == 0) st_rel(fout + t, 1u);
    }
}

// ---------------------------------------------------------------------------
// 128 CTAs x 384 threads (3 warpgroups):
//  WG0/WG1: stack3 layer (cta>>1), quarter-batch splits 2*(cta&1), 2*(cta&1)+1
//           (shared smem weight copy)
//  WG2: cta<64 -> stack2 layer cta; cta in [64,80) -> stack1 pack2; else idle
// ---------------------------------------------------------------------------
__global__ void __launch_bounds__(384, 1)
lstm_pipe(const float* l1_Wih0, const float* l1_Whh0, const float* l1_bih0, const float* l1_bhh0,
          const float* l1_Wih,  const float* l1_Whh,  const float* l1_bih,  const float* l1_bhh,
          const float* l2_Wih0, const float* l2_Whh0, const float* l2_bih0, const float* l2_bhh0,
          const float* l2_Wih,  const float* l2_Whh,  const float* l2_bih,  const float* l2_bhh,
          const float* l3_Wih0, const float* l3_Whh0, const float* l3_bih0, const float* l3_bhh0,
          const float* l3_Wih,  const float* l3_Whh,  const float* l3_bih,  const float* l3_bhh)
{
    __shared__ float sW0[64 * 32];                     // 8KB  s3 weights (shared WG0/WG1)
    __shared__ float sB0[64];
    __shared__ __align__(16) float2 rows0a[2 * 16 * 32];  // 8KB  WG0 rows
    __shared__ __align__(16) float2 rows0b[2 * 16 * 32];  // 8KB  WG1 rows
    __shared__ float sW1[512];                         // 2KB  s2 / s1-pack2
    __shared__ float sB1[64];
    __shared__ __align__(16) float2 rows1[2048];       // 16KB WG2 rows

    const int tid = threadIdx.x, cta = blockIdx.x;
    const int d = cta >> 1;

    // --- init fills ---
    if (tid < 256) {
        fill_s<16, 8>(sW0, sB0, l3_Wih0, l3_Whh0, l3_bih0, l3_bhh0,
                      l3_Wih, l3_Whh, l3_bih, l3_bhh, d, tid, 256);
        if (tid < 128)
            for (int i = tid; i < 2 * 16 * 32; i += WG) rows0a[i] = make_float2(0.f, 0.f);
        else
            for (int i = tid - 128; i < 2 * 16 * 32; i += WG) rows0b[i] = make_float2(0.f, 0.f);
    } else {
        const int wtid = tid - 256;
        if (cta < 64) {
            fill_s<8, 4>(sW1, sB1, l2_Wih0, l2_Whh0, l2_bih0, l2_bhh0,
                         l2_Wih, l2_Whh, l2_bih, l2_bhh, cta, wtid, WG);
        } else if (cta < 80) {
            const int i0 = cta - 64;
            fill_s<4, 2>(sW1, sB1, l1_Wih0, l1_Whh0, l1_bih0, l1_bhh0,
                         l1_Wih, l1_Whh, l1_bih, l1_bhh, 2 * i0, wtid, WG);
            fill_s<4, 2>(sW1 + 128, sB1 + 16, l1_Wih0, l1_Whh0, l1_bih0, l1_bhh0,
                         l1_Wih, l1_Whh, l1_bih, l1_bhh, 2 * i0 + 1, wtid, WG);
        }
        for (int i = wtid; i < 2048; i += WG) rows1[i] = make_float2(0.f, 0.f);
    }
    __syncthreads();

    if (tid < 256) {
        // ---- WG0/WG1: stack3 quarter-batch ----
        const int wgi = tid >> 7;               // 0 or 1
        const int wtid = tid & 127;
        const int s = (cta & 1) * 2 + wgi;
        const int q = 80 + d;
        const float* bufin = g_act[q & 1];
        float* bufout = g_act[(q + 1) & 1];
        const unsigned* fin = (d == 0) ? FLAG(79, 0) : FLAG(q - 1, s);
        unsigned* fout = FLAG(q, s);
        float2* rows = wgi ? rows0b : rows0a;
        const int b0 = s * 64;
        const int barid = 1 + wgi;
        if (d == 0)
            stage_loop<16, 1, 32, 8, false, true, false>(sW0, sB0, rows, bufin, bufout, fin, fout, b0, wtid, barid);
        else if (d == 63)
            stage_loop<16, 1, 32, 16, false, false, true>(sW0, sB0, rows, bufin, bufout, fin, fout, b0, wtid, barid);
        else
            stage_loop<16, 1, 32, 16, false, false, false>(sW0, sB0, rows, bufin, bufout, fin, fout, b0, wtid, barid);
    } else if (cta < 64) {
        // ---- WG2: stack2 single layer, full batch ----
        const int wtid = tid - 256;
        const int u = cta, q = 16 + u;
        const float* bufin = g_act[q & 1];
        float* bufout = g_act[(q + 1) & 1];
        const unsigned* fin = FLAG(q - 1, 0);
        unsigned* fout = FLAG(q, 0);
        if (u == 0)
            stage_loop<8, 1, 128, 4, false, true, false>(sW1, sB1, rows1, bufin, bufout, fin, fout, 0, wtid, 3);
        else
            stage_loop<8, 1, 128, 8, false, false, false>(sW1, sB1, rows1, bufin, bufout, fin, fout, 0, wtid, 3);
    } else if (cta < 80) {
        // ---- WG2: stack1 pack2, full batch ----
        const int wtid = tid - 256;
        const int i0 = cta - 64, q = i0;
        const float* bufin = g_act[q & 1];
        float* bufout = g_act[(q + 1) & 1];
        const unsigned* fin = FLAG(q > 0 ? q - 1 : 0, 0);
        unsigned* fout = FLAG(q, 0);
        if (i0 == 0)
            stage_loop<4, 2, 128, 2, true, false, false>(sW1, sB1, rows1, bufin, bufout, fin, fout, 0, wtid, 3);
        else
            stage_loop<4, 2, 128, 4, false, false, false>(sW1, sB1, rows1, bufin, bufout, fin, fout, 0, wtid, 3);
    }
}

// ---------------------------------------------------------------------------
// Pre: transpose x -> g_act[0][t][m][b] AND clear all flags (replay-safe).
// Post: ReLU + FC(16->4).
// ---------------------------------------------------------------------------
__global__ void pre_kernel(const float* __restrict__ x) {
    int t = blockIdx.x, b = threadIdx.x;
    float2 v = *reinterpret_cast<const float2*>(&x[((size_t)t * BATCH + b) * 2]);
    g_act[0][(t * 16 + 0) * BATCH + b] = v.x;
    g_act[0][(t * 16 + 1) * BATCH + b] = v.y;
    int idx = t * BATCH + b;
    for (int i = idx; i < NSTAGES * 4 * T_STEPS; i += T_STEPS * BATCH)
        g_flags[i] = 0;
}

__global__ void fc_kernel(const float* __restrict__ fcW, const float* __restrict__ fcb,
                          float* __restrict__ out) {
    int t = blockIdx.x, b = threadIdx.x;
    float v[16];
#pragma unroll
    for (int m = 0; m < 16; m++)
        v[m] = fmaxf(g_act[0][(t * 16 + m) * BATCH + b], 0.f);
#pragma unroll
    for (int q = 0; q < 4; q++) {
        float a = fcb[q];
#pragma unroll
        for (int m = 0; m < 16; m++) a = fmaf(v[m], fcW[q * 16 + m], a);
        out[((size_t)t * BATCH + b) * 4 + q] = a;
    }
}

// ---------------------------------------------------------------------------
extern "C" void kernel_launch(void* const* d_in, const int* in_sizes, int n_in,
                              void* d_out, int out_size) {
#define F(i) ((const float*)d_in[i])
    pre_kernel<<<T_STEPS, BATCH>>>(F(0));
    lstm_pipe<<<128, 384>>>(
        F(1), F(2), F(3), F(4), F(5), F(6), F(7), F(8),
        F(9), F(10), F(11), F(12), F(13), F(14), F(15), F(16),
        F(17), F(18), F(19), F(20), F(21), F(22), F(23), F(24));
    fc_kernel<<<T_STEPS, BATCH>>>(F(25), F(26), (float*)d_out);
#undef F
}

// round 7
// speedup vs baseline: 1.1113x; 1.1113x over previous
#include <cuda_runtime.h>

#define T_STEPS 512
#define BATCH   256
#define NSTAGES 144     // q: s1 0..15, s2 16..79, s3 80..143

// Ping-pong activation buffers, layout [t][feature(16)][batch]
__device__ __align__(16) float g_act[2][T_STEPS * 16 * BATCH];
// Flags [stage][split(2)][t]; cleared by pre_kernel each replay.
__device__ unsigned g_flags[NSTAGES * 2 * T_STEPS];

#define FLAG(q, s) (g_flags + ((size_t)(q) * 2 + (s)) * T_STEPS)

// ---------------------------------------------------------------------------
__device__ __forceinline__ unsigned ld_acq(const unsigned* p) {
    unsigned v;
    asm volatile("ld.acquire.gpu.global.u32 %0, [%1];" : "=r"(v) : "l"(p) : "memory");
    return v;
}
__device__ __forceinline__ void st_rel(unsigned* p, unsigned v) {
    asm volatile("st.release.gpu.global.u32 [%0], %1;" :: "l"(p), "r"(v) : "memory");
}
__device__ __forceinline__ float2 ffma2(float2 a, float2 b, float2 c) {
    float2 d;
    asm("fma.rn.f32x2 %0, %1, %2, %3;"
        : "=l"(reinterpret_cast<unsigned long long&>(d))
        : "l"(reinterpret_cast<unsigned long long&>(a)),
          "l"(reinterpret_cast<unsigned long long&>(b)),
          "l"(reinterpret_cast<unsigned long long&>(c)));
    return d;
}
__device__ __forceinline__ void wg_bar(int id, int nthr) {
    asm volatile("bar.sync %0, %1;" :: "r"(id), "r"(nthr) : "memory");
}

// Exact LSTM nonlinearity, shared-denominator form: 5 ex2 + 2 rcp.
// Gate clamps dropped (|gate| < 9 by weight-norm bound); c-clamp kept
// (guards exp(-2c) overflow; tanh saturated beyond +-15 anyway).
__device__ __forceinline__ float cell_one(float gi, float gf, float gg, float go,
                                          float& c) {
    float a  = __expf(-gi);
    float fe = __expf(-gf);
    float b  = __expf(-2.f * gg);
    float na = 1.f + a, nf = 1.f + fe, nb = 1.f + b;
    float num = fmaf(c * na, nb, (1.f - b) * nf);
    c = __fdividef(num, nf * na * nb);
    float ct = fminf(fmaxf(c, -15.f), 15.f);
    float d  = __expf(-2.f * ct);
    float oe = __expf(-go);
    return __fdividef(1.f - d, (1.f + oe) * (1.f + d));
}

// ---------------------------------------------------------------------------
// Gate-packed weight fill: W4[k*H + j] = {w_i, w_f, w_g, w_o} for (k, j).
// k<din from Wih, [din,H) zero, [H,2H) from Whh.  B4[j] = packed gate biases.
// ---------------------------------------------------------------------------
template<int H, int DIN0>
__device__ void fill_s4(float4* W4, float4* B4,
                        const float* Wih0, const float* Whh0,
                        const float* bih0, const float* bhh0,
                        const float* Wih,  const float* Whh,
                        const float* bih,  const float* bhh,
                        int l, int wtid, int stride) {
    constexpr int G = 4 * H, KM = 2 * H;
    const float* wi = l ? Wih + (size_t)(l - 1) * G * H : Wih0;
    const float* wh = l ? Whh + (size_t)(l - 1) * G * H : Whh0;
    const float* bi = l ? bih + (l - 1) * G : bih0;
    const float* bh = l ? bhh + (l - 1) * G : bhh0;
    const int din = l ? H : DIN0;
    for (int i = wtid; i < KM * H; i += stride) {
        int k = i / H, j = i % H;
        float v[4];
#pragma unroll
        for (int g = 0; g < 4; g++) {
            float w = 0.f;
            if (k < din)     w = wi[(g * H + j) * din + k];
            else if (k >= H) w = wh[(g * H + j) * H + (k - H)];
            v[g] = w;
        }
        W4[i] = make_float4(v[0], v[1], v[2], v[3]);
    }
    for (int jj = wtid; jj < H; jj += stride)
        B4[jj] = make_float4(bi[0 * H + jj] + bh[0 * H + jj],
                             bi[1 * H + jj] + bh[1 * H + jj],
                             bi[2 * H + jj] + bh[2 * H + jj],
                             bi[3 * H + jj] + bh[3 * H + jj]);
}

// ---------------------------------------------------------------------------
// Stage loop. rows: [0,H) staged input (rows [DSTAGE,H) stay zero),
// pack p's h at [(p+1)H,(p+2)H).  Pack 0 is split h-part / x-part so the
// global x loads overlap the h-recurrent FMA.  2 bars/step (PACK=1),
// 3 bars/step (PACK=2).
// ---------------------------------------------------------------------------
template<int H, int PACK, int BPC_, int DSTAGE, int NTHR, bool FIRST, bool RELU, bool LAST>
__device__ void stage_loop(const float4* __restrict__ sW, const float4* __restrict__ sB,
                           float2* rows,
                           const float* __restrict__ bufin, float* __restrict__ bufout,
                           const unsigned* fin, unsigned* fout, int b0,
                           int wtid, int barid) {
    constexpr int GROUPS = NTHR / H;
    constexpr int NB = BPC_ / GROUPS;
    constexpr int KM = 2 * H;
    constexpr int QROW = BPC_ / 2;               // float4 slots per feature row
    constexpr int NLD = DSTAGE * QROW / NTHR;    // divides exactly in all configs
    const int j = wtid / GROUPS, group = wtid % GROUPS;

    float2 c[PACK][NB];
#pragma unroll
    for (int p = 0; p < PACK; p++)
#pragma unroll
        for (int n = 0; n < NB; n++) c[p][n] = make_float2(0.f, 0.f);

    for (int i = wtid; i < (PACK + 1) * H * BPC_; i += NTHR)
        rows[i] = make_float2(0.f, 0.f);
    wg_bar(barid, NTHR);

    for (int t = 0; t < T_STEPS; t++) {
        // --- poll + issue x loads (consumed only at commit; overlap h-FMA) ---
        if (!FIRST) { const unsigned* f = fin + t; while (ld_acq(f) == 0) { } }
        float4 pf[NLD];
        const float* bin = bufin + (size_t)t * 16 * BATCH + b0;
#pragma unroll
        for (int L = 0; L < NLD; L++) {
            int i = wtid + L * NTHR;
            int m = i / QROW, q4 = i % QROW;
            pf[L] = __ldcg(reinterpret_cast<const float4*>(&bin[m * BATCH + 4 * q4]));
        }

        // --- pack 0: bias init + h-recurrent half ---
        float2 acc[4][NB];
        {
            float4 bv = sB[j];
#pragma unroll
            for (int n = 0; n < NB; n++) {
                acc[0][n] = make_float2(bv.x, bv.x);
                acc[1][n] = make_float2(bv.y, bv.y);
                acc[2][n] = make_float2(bv.z, bv.z);
                acc[3][n] = make_float2(bv.w, bv.w);
            }
        }
#pragma unroll 4
        for (int k = H; k < KM; k++) {
            float4 wv = sW[k * H + j];
            float2 w0 = make_float2(wv.x, wv.x), w1 = make_float2(wv.y, wv.y);
            float2 w2 = make_float2(wv.z, wv.z), w3 = make_float2(wv.w, wv.w);
#pragma unroll
            for (int n = 0; n < NB; n++) {
                float2 v = rows[k * BPC_ + n * GROUPS + group];
                acc[0][n] = ffma2(w0, v, acc[0][n]);
                acc[1][n] = ffma2(w1, v, acc[1][n]);
                acc[2][n] = ffma2(w2, v, acc[2][n]);
                acc[3][n] = ffma2(w3, v, acc[3][n]);
            }
        }
        // --- commit staged x to smem ---
#pragma unroll
        for (int L = 0; L < NLD; L++) {
            int i = wtid + L * NTHR;
            int m = i / QROW, q4 = i % QROW;
            float4 v = pf[L];
            if (RELU) {
                v.x = fmaxf(v.x, 0.f); v.y = fmaxf(v.y, 0.f);
                v.z = fmaxf(v.z, 0.f); v.w = fmaxf(v.w, 0.f);
            }
            *reinterpret_cast<float4*>(&rows[m * BPC_ + 2 * q4]) = v;
        }
        wg_bar(barid, NTHR);   // x(t) visible; everyone past h-part reads

        // --- pack 0: x half ---
#pragma unroll 4
        for (int k = 0; k < DSTAGE; k++) {
            float4 wv = sW[k * H + j];
            float2 w0 = make_float2(wv.x, wv.x), w1 = make_float2(wv.y, wv.y);
            float2 w2 = make_float2(wv.z, wv.z), w3 = make_float2(wv.w, wv.w);
#pragma unroll
            for (int n = 0; n < NB; n++) {
                float2 v = rows[k * BPC_ + n * GROUPS + group];
                acc[0][n] = ffma2(w0, v, acc[0][n]);
                acc[1][n] = ffma2(w1, v, acc[1][n]);
                acc[2][n] = ffma2(w2, v, acc[2][n]);
                acc[3][n] = ffma2(w3, v, acc[3][n]);
            }
        }
        // --- pack 0 activations + h write (safe after bar: h readers done) ---
        float* bout = bufout + (size_t)t * 16 * BATCH + b0;
        {
            float2 h2[NB];
#pragma unroll
            for (int n = 0; n < NB; n++) {
                h2[n].x = cell_one(acc[0][n].x, acc[1][n].x, acc[2][n].x,
                                   acc[3][n].x, c[0][n].x);
                h2[n].y = cell_one(acc[0][n].y, acc[1][n].y, acc[2][n].y,
                                   acc[3][n].y, c[0][n].y);
            }
            float2* hrow = rows + H * BPC_ + j * BPC_;
#pragma unroll
            for (int n = 0; n < NB; n++) {
                int bp = n * GROUPS + group;
                hrow[bp] = h2[n];
                if (PACK == 1)
                    *reinterpret_cast<float2*>(&bout[j * BATCH + 2 * bp]) = h2[n];
            }
        }

        if (PACK > 1) {
            wg_bar(barid, NTHR);   // pack0 h visible to pack1
#pragma unroll
            for (int p = 1; p < PACK; p++) {
                const float2* vin = rows + p * H * BPC_;
                float4 bv = sB[p * H + j];
#pragma unroll
                for (int n = 0; n < NB; n++) {
                    acc[0][n] = make_float2(bv.x, bv.x);
                    acc[1][n] = make_float2(bv.y, bv.y);
                    acc[2][n] = make_float2(bv.z, bv.z);
                    acc[3][n] = make_float2(bv.w, bv.w);
                }
#pragma unroll 4
                for (int k = 0; k < KM; k++) {
                    float4 wv = sW[p * KM * H + k * H + j];
                    float2 w0 = make_float2(wv.x, wv.x), w1 = make_float2(wv.y, wv.y);
                    float2 w2 = make_float2(wv.z, wv.z), w3 = make_float2(wv.w, wv.w);
#pragma unroll
                    for (int n = 0; n < NB; n++) {
                        float2 v = vin[k * BPC_ + n * GROUPS + group];
                        acc[0][n] = ffma2(w0, v, acc[0][n]);
                        acc[1][n] = ffma2(w1, v, acc[1][n]);
                        acc[2][n] = ffma2(w2, v, acc[2][n]);
                        acc[3][n] = ffma2(w3, v, acc[3][n]);
                    }
                }
                float2 h2[NB];
#pragma unroll
                for (int n = 0; n < NB; n++) {
                    h2[n].x = cell_one(acc[0][n].x, acc[1][n].x, acc[2][n].x,
                                       acc[3][n].x, c[p][n].x);
                    h2[n].y = cell_one(acc[0][n].y, acc[1][n].y, acc[2][n].y,
                                       acc[3][n].y, c[p][n].y);
                }
                wg_bar(barid, NTHR);   // all reads of pack-p inputs done
                float2* hrow = rows + (p + 1) * H * BPC_ + j * BPC_;
#pragma unroll
                for (int n = 0; n < NB; n++) {
                    int bp = n * GROUPS + group;
                    hrow[bp] = h2[n];
                    if (p == PACK - 1)
                        *reinterpret_cast<float2*>(&bout[j * BATCH + 2 * bp]) = h2[n];
                }
            }
        }

        if (!LAST && wtid == 0) st_rel(fout + t, 1u);
        if (PACK == 1) wg_bar(barid, NTHR);   // h(t) visible before next h-part
        // PACK>1: next-step reads covered by this step's inner bars + next bar
    }
}

// ---------------------------------------------------------------------------
// 128 CTAs x 384 threads:
//  tid<256 (8 warps): stack3 layer (cta>>1), batch half (cta&1), BPC=64
//  tid>=256 (4 warps): cta<64 -> stack2 layer cta; cta in [64,80) -> stack1
//                      pack2; else idle
// ---------------------------------------------------------------------------
__global__ void __launch_bounds__(384, 1)
lstm_pipe(const float* l1_Wih0, const float* l1_Whh0, const float* l1_bih0, const float* l1_bhh0,
          const float* l1_Wih,  const float* l1_Whh,  const float* l1_bih,  const float* l1_bhh,
          const float* l2_Wih0, const float* l2_Whh0, const float* l2_bih0, const float* l2_bhh0,
          const float* l2_Wih,  const float* l2_Whh,  const float* l2_bih,  const float* l2_bhh,
          const float* l3_Wih0, const float* l3_Whh0, const float* l3_bih0, const float* l3_bhh0,
          const float* l3_Wih,  const float* l3_Whh,  const float* l3_bih,  const float* l3_bhh)
{
    __shared__ __align__(16) float4 sW0[32 * 16];   // 8KB  s3 weights (gate-packed)
    __shared__ __align__(16) float4 sB0[16];
    __shared__ __align__(16) float2 rows0[2 * 16 * 64];   // 16KB s3 rows
    __shared__ __align__(16) float4 sW1[128];       // 2KB  s2 / s1-pack2 weights
    __shared__ __align__(16) float4 sB1[16];
    __shared__ __align__(16) float2 rows1[2048];    // 16KB WG2 rows

    const int tid = threadIdx.x, cta = blockIdx.x;
    const int d = cta >> 1;

    if (tid < 256) {
        fill_s4<16, 8>(sW0, sB0, l3_Wih0, l3_Whh0, l3_bih0, l3_bhh0,
                       l3_Wih, l3_Whh, l3_bih, l3_bhh, d, tid, 256);
    } else {
        const int wtid = tid - 256;
        if (cta < 64) {
            fill_s4<8, 4>(sW1, sB1, l2_Wih0, l2_Whh0, l2_bih0, l2_bhh0,
                          l2_Wih, l2_Whh, l2_bih, l2_bhh, cta, wtid, 128);
        } else if (cta < 80) {
            const int i0 = cta - 64;
            fill_s4<4, 2>(sW1, sB1, l1_Wih0, l1_Whh0, l1_bih0, l1_bhh0,
                          l1_Wih, l1_Whh, l1_bih, l1_bhh, 2 * i0, wtid, 128);
            fill_s4<4, 2>(sW1 + 8 * 4, sB1 + 4, l1_Wih0, l1_Whh0, l1_bih0, l1_bhh0,
                          l1_Wih, l1_Whh, l1_bih, l1_bhh, 2 * i0 + 1, wtid, 128);
        }
    }
    __syncthreads();

    if (tid < 256) {
        // ---- stack3: half batch, 256 threads ----
        const int wtid = tid;
        const int s = cta & 1;
        const int q = 80 + d;
        const float* bufin = g_act[q & 1];
        float* bufout = g_act[(q + 1) & 1];
        const unsigned* fin = (d == 0) ? FLAG(79, 0) : FLAG(q - 1, s);
        unsigned* fout = FLAG(q, s);
        const int b0 = s * 128;
        if (d == 0)
            stage_loop<16, 1, 64, 8, 256, false, true, false>(sW0, sB0, rows0, bufin, bufout, fin, fout, b0, wtid, 1);
        else if (d == 63)
            stage_loop<16, 1, 64, 16, 256, false, false, true>(sW0, sB0, rows0, bufin, bufout, fin, fout, b0, wtid, 1);
        else
            stage_loop<16, 1, 64, 16, 256, false, false, false>(sW0, sB0, rows0, bufin, bufout, fin, fout, b0, wtid, 1);
    } else if (cta < 64) {
        // ---- stack2: single layer, full batch, 128 threads ----
        const int wtid = tid - 256;
        const int u = cta, q = 16 + u;
        const float* bufin = g_act[q & 1];
        float* bufout = g_act[(q + 1) & 1];
        const unsigned* fin = FLAG(q - 1, 0);
        unsigned* fout = FLAG(q, 0);
        if (u == 0)
            stage_loop<8, 1, 128, 4, 128, false, true, false>(sW1, sB1, rows1, bufin, bufout, fin, fout, 0, wtid, 2);
        else
            stage_loop<8, 1, 128, 8, 128, false, false, false>(sW1, sB1, rows1, bufin, bufout, fin, fout, 0, wtid, 2);
    } else if (cta < 80) {
        // ---- stack1: pack2, full batch, 128 threads ----
        const int wtid = tid - 256;
        const int i0 = cta - 64, q = i0;
        const float* bufin = g_act[q & 1];
        float* bufout = g_act[(q + 1) & 1];
        const unsigned* fin = FLAG(q > 0 ? q - 1 : 0, 0);
        unsigned* fout = FLAG(q, 0);
        if (i0 == 0)
            stage_loop<4, 2, 128, 2, 128, true, false, false>(sW1, sB1, rows1, bufin, bufout, fin, fout, 0, wtid, 2);
        else
            stage_loop<4, 2, 128, 4, 128, false, false, false>(sW1, sB1, rows1, bufin, bufout, fin, fout, 0, wtid, 2);
    }
}

// ---------------------------------------------------------------------------
// Pre: transpose x -> g_act[0][t][m][b] AND clear all flags (replay-safe).
// Post: ReLU + FC(16->4).
// ---------------------------------------------------------------------------
__global__ void pre_kernel(const float* __restrict__ x) {
    int t = blockIdx.x, b = threadIdx.x;
    float2 v = *reinterpret_cast<const float2*>(&x[((size_t)t * BATCH + b) * 2]);
    g_act[0][(t * 16 + 0) * BATCH + b] = v.x;
    g_act[0][(t * 16 + 1) * BATCH + b] = v.y;
    int idx = t * BATCH + b;
    for (int i = idx; i < NSTAGES * 2 * T_STEPS; i += T_STEPS * BATCH)
        g_flags[i] = 0;
}

__global__ void fc_kernel(const float* __restrict__ fcW, const float* __restrict__ fcb,
                          float* __restrict__ out) {
    int t = blockIdx.x, b = threadIdx.x;
    float v[16];
#pragma unroll
    for (int m = 0; m < 16; m++)
        v[m] = fmaxf(g_act[0][(t * 16 + m) * BATCH + b], 0.f);
#pragma unroll
    for (int q = 0; q < 4; q++) {
        float a = fcb[q];
#pragma unroll
        for (int m = 0; m < 16; m++) a = fmaf(v[m], fcW[q * 16 + m], a);
        out[((size_t)t * BATCH + b) * 4 + q] = a;
    }
}

// ---------------------------------------------------------------------------
extern "C" void kernel_launch(void* const* d_in, const int* in_sizes, int n_in,
                              void* d_out, int out_size) {
#define F(i) ((const float*)d_in[i])
    pre_kernel<<<T_STEPS, BATCH>>>(F(0));
    lstm_pipe<<<128, 384>>>(
        F(1), F(2), F(3), F(4), F(5), F(6), F(7), F(8),
        F(9), F(10), F(11), F(12), F(13), F(14), F(15), F(16),
        F(17), F(18), F(19), F(20), F(21), F(22), F(23), F(24));
    fc_kernel<<<T_STEPS, BATCH>>>(F(25), F(26), (float*)d_out);
#undef F
}

// round 8
// speedup vs baseline: 1.1538x; 1.0382x over previous
#include <cuda_runtime.h>

#define T_STEPS 512
#define BATCH   256
#define NSTAGES 144     // q: s1 0..15, s2 16..79, s3 80..143

// Ping-pong activation buffers, layout [t][feature(16)][batch]
__device__ __align__(16) float g_act[2][T_STEPS * 16 * BATCH];
// Flags [stage][split(2)][t]; cleared by pre_kernel each replay.
__device__ unsigned g_flags[NSTAGES * 2 * T_STEPS];

#define FLAG(q, s) (g_flags + ((size_t)(q) * 2 + (s)) * T_STEPS)

// ---------------------------------------------------------------------------
__device__ __forceinline__ unsigned ld_acq(const unsigned* p) {
    unsigned v;
    asm volatile("ld.acquire.gpu.global.u32 %0, [%1];" : "=r"(v) : "l"(p) : "memory");
    return v;
}
__device__ __forceinline__ void st_rel(unsigned* p, unsigned v) {
    asm volatile("st.release.gpu.global.u32 [%0], %1;" :: "l"(p), "r"(v) : "memory");
}
__device__ __forceinline__ float2 ffma2(float2 a, float2 b, float2 c) {
    float2 d;
    asm("fma.rn.f32x2 %0, %1, %2, %3;"
        : "=l"(reinterpret_cast<unsigned long long&>(d))
        : "l"(reinterpret_cast<unsigned long long&>(a)),
          "l"(reinterpret_cast<unsigned long long&>(b)),
          "l"(reinterpret_cast<unsigned long long&>(c)));
    return d;
}
__device__ __forceinline__ void wg_bar(int id, int nthr) {
    asm volatile("bar.sync %0, %1;" :: "r"(id), "r"(nthr) : "memory");
}

// Exact LSTM nonlinearity, shared-denominator form: 5 ex2 + 2 rcp.
__device__ __forceinline__ float cell_one(float gi, float gf, float gg, float go,
                                          float& c) {
    float a  = __expf(-gi);
    float fe = __expf(-gf);
    float b  = __expf(-2.f * gg);
    float na = 1.f + a, nf = 1.f + fe, nb = 1.f + b;
    float num = fmaf(c * na, nb, (1.f - b) * nf);
    c = __fdividef(num, nf * na * nb);
    float ct = fminf(fmaxf(c, -15.f), 15.f);
    float d  = __expf(-2.f * ct);
    float oe = __expf(-go);
    return __fdividef(1.f - d, (1.f + oe) * (1.f + d));
}

// ---------------------------------------------------------------------------
// Gate-packed weight fill: W4[k*H + j] = {w_i, w_f, w_g, w_o} for (k, j).
// ---------------------------------------------------------------------------
template<int H, int DIN0>
__device__ void fill_s4(float4* W4, float4* B4,
                        const float* Wih0, const float* Whh0,
                        const float* bih0, const float* bhh0,
                        const float* Wih,  const float* Whh,
                        const float* bih,  const float* bhh,
                        int l, int wtid, int stride) {
    constexpr int G = 4 * H, KM = 2 * H;
    const float* wi = l ? Wih + (size_t)(l - 1) * G * H : Wih0;
    const float* wh = l ? Whh + (size_t)(l - 1) * G * H : Whh0;
    const float* bi = l ? bih + (l - 1) * G : bih0;
    const float* bh = l ? bhh + (l - 1) * G : bhh0;
    const int din = l ? H : DIN0;
    for (int i = wtid; i < KM * H; i += stride) {
        int k = i / H, j = i % H;
        float v[4];
#pragma unroll
        for (int g = 0; g < 4; g++) {
            float w = 0.f;
            if (k < din)     w = wi[(g * H + j) * din + k];
            else if (k >= H) w = wh[(g * H + j) * H + (k - H)];
            v[g] = w;
        }
        W4[i] = make_float4(v[0], v[1], v[2], v[3]);
    }
    for (int jj = wtid; jj < H; jj += stride)
        B4[jj] = make_float4(bi[0 * H + jj] + bh[0 * H + jj],
                             bi[1 * H + jj] + bh[1 * H + jj],
                             bi[2 * H + jj] + bh[2 * H + jj],
                             bi[3 * H + jj] + bh[3 * H + jj]);
}

// ---------------------------------------------------------------------------
// Stage loop. rows: [0,H) x (rows [DSTAGE,H) stay zero), pack-p h at
// [(p+1)H,(p+2)H).  Order per step:
//   P1 pack0 recurrent FMA (hides poll/LDG latency behind local work)
//   P2 poll + x LDG + smem commit + bar
//   P3 pack0 x-part FMA + activations + h0 write (+ gout if PACK==1)
//   [PACK==2: bar, pack1 full FMA + act, bar, h1 write + gout]
//   end bar, then flag release (cta-bar -> gpu-release publishes all STGs)
// ---------------------------------------------------------------------------
template<int H, int PACK, int BPC_, int DSTAGE, int NTHR, bool FIRST, bool RELU, bool LAST>
__device__ void stage_loop(const float4* __restrict__ sW, const float4* __restrict__ sB,
                           float2* rows,
                           const float* __restrict__ bufin, float* __restrict__ bufout,
                           const unsigned* fin, unsigned* fout, int b0,
                           int wtid, int barid) {
    constexpr int GROUPS = NTHR / H;
    constexpr int NB = BPC_ / GROUPS;
    constexpr int KM = 2 * H;
    constexpr int QROW = BPC_ / 2;               // float4 slots per feature row
    constexpr int NQ = DSTAGE * QROW;
    constexpr int NLD = (NQ + NTHR - 1) / NTHR;
    const int j = wtid / GROUPS, group = wtid % GROUPS;

    float2 c[PACK][NB];
#pragma unroll
    for (int p = 0; p < PACK; p++)
#pragma unroll
        for (int n = 0; n < NB; n++) c[p][n] = make_float2(0.f, 0.f);

    for (int i = wtid; i < (PACK + 1) * H * BPC_; i += NTHR)
        rows[i] = make_float2(0.f, 0.f);
    wg_bar(barid, NTHR);

    for (int t = 0; t < T_STEPS; t++) {
        // --- P1: pack0 recurrent half (h(t-1) already in smem) ---
        float2 acc[4][NB];
        {
            float4 bv = sB[j];
#pragma unroll
            for (int n = 0; n < NB; n++) {
                acc[0][n] = make_float2(bv.x, bv.x);
                acc[1][n] = make_float2(bv.y, bv.y);
                acc[2][n] = make_float2(bv.z, bv.z);
                acc[3][n] = make_float2(bv.w, bv.w);
            }
        }
#pragma unroll 4
        for (int k = H; k < KM; k++) {
            float4 wv = sW[k * H + j];
            float2 w0 = make_float2(wv.x, wv.x), w1 = make_float2(wv.y, wv.y);
            float2 w2 = make_float2(wv.z, wv.z), w3 = make_float2(wv.w, wv.w);
#pragma unroll
            for (int n = 0; n < NB; n++) {
                float2 v = rows[k * BPC_ + n * GROUPS + group];
                acc[0][n] = ffma2(w0, v, acc[0][n]);
                acc[1][n] = ffma2(w1, v, acc[1][n]);
                acc[2][n] = ffma2(w2, v, acc[2][n]);
                acc[3][n] = ffma2(w3, v, acc[3][n]);
            }
        }

        // --- P2: poll + x loads + commit ---
        if (!FIRST) { const unsigned* f = fin + t; while (ld_acq(f) == 0) { } }
        const float* bin = bufin + (size_t)t * 16 * BATCH + b0;
        float4 pf[NLD];
#pragma unroll
        for (int L = 0; L < NLD; L++) {
            int i = wtid + L * NTHR;
            if (NQ % NTHR == 0 || i < NQ) {
                int m = i / QROW, q4 = i % QROW;
                pf[L] = __ldcg(reinterpret_cast<const float4*>(&bin[m * BATCH + 4 * q4]));
            }
        }
#pragma unroll
        for (int L = 0; L < NLD; L++) {
            int i = wtid + L * NTHR;
            if (NQ % NTHR == 0 || i < NQ) {
                int m = i / QROW, q4 = i % QROW;
                float4 v = pf[L];
                if (RELU) {
                    v.x = fmaxf(v.x, 0.f); v.y = fmaxf(v.y, 0.f);
                    v.z = fmaxf(v.z, 0.f); v.w = fmaxf(v.w, 0.f);
                }
                *reinterpret_cast<float4*>(&rows[m * BPC_ + 2 * q4]) = v;
            }
        }
        wg_bar(barid, NTHR);   // x(t) visible; all P1 h-reads complete

        // --- P3: pack0 x half + activations + h0 write ---
#pragma unroll 4
        for (int k = 0; k < DSTAGE; k++) {
            float4 wv = sW[k * H + j];
            float2 w0 = make_float2(wv.x, wv.x), w1 = make_float2(wv.y, wv.y);
            float2 w2 = make_float2(wv.z, wv.z), w3 = make_float2(wv.w, wv.w);
#pragma unroll
            for (int n = 0; n < NB; n++) {
                float2 v = rows[k * BPC_ + n * GROUPS + group];
                acc[0][n] = ffma2(w0, v, acc[0][n]);
                acc[1][n] = ffma2(w1, v, acc[1][n]);
                acc[2][n] = ffma2(w2, v, acc[2][n]);
                acc[3][n] = ffma2(w3, v, acc[3][n]);
            }
        }
        float* bout = bufout + (size_t)t * 16 * BATCH + b0;
        {
            float2 h2[NB];
#pragma unroll
            for (int n = 0; n < NB; n++) {
                h2[n].x = cell_one(acc[0][n].x, acc[1][n].x, acc[2][n].x,
                                   acc[3][n].x, c[0][n].x);
                h2[n].y = cell_one(acc[0][n].y, acc[1][n].y, acc[2][n].y,
                                   acc[3][n].y, c[0][n].y);
            }
            float2* hrow = rows + H * BPC_ + j * BPC_;
#pragma unroll
            for (int n = 0; n < NB; n++) {
                int bp = n * GROUPS + group;
                hrow[bp] = h2[n];
                if (PACK == 1)
                    *reinterpret_cast<float2*>(&bout[j * BATCH + 2 * bp]) = h2[n];
            }
        }

        if (PACK > 1) {
            wg_bar(barid, NTHR);   // h0(t) visible
            // pack1: input = h0(t) rows [H,2H), recurrent = h1(t-1) rows [2H,3H)
            float2 acc1[4][NB];
            {
                float4 bv = sB[H + j];
#pragma unroll
                for (int n = 0; n < NB; n++) {
                    acc1[0][n] = make_float2(bv.x, bv.x);
                    acc1[1][n] = make_float2(bv.y, bv.y);
                    acc1[2][n] = make_float2(bv.z, bv.z);
                    acc1[3][n] = make_float2(bv.w, bv.w);
                }
            }
#pragma unroll 4
            for (int k = 0; k < KM; k++) {
                float4 wv = sW[KM * H + k * H + j];
                float2 w0 = make_float2(wv.x, wv.x), w1 = make_float2(wv.y, wv.y);
                float2 w2 = make_float2(wv.z, wv.z), w3 = make_float2(wv.w, wv.w);
#pragma unroll
                for (int n = 0; n < NB; n++) {
                    float2 v = rows[(H + k) * BPC_ + n * GROUPS + group];
                    acc1[0][n] = ffma2(w0, v, acc1[0][n]);
                    acc1[1][n] = ffma2(w1, v, acc1[1][n]);
                    acc1[2][n] = ffma2(w2, v, acc1[2][n]);
                    acc1[3][n] = ffma2(w3, v, acc1[3][n]);
                }
            }
            float2 h2[NB];
#pragma unroll
            for (int n = 0; n < NB; n++) {
                h2[n].x = cell_one(acc1[0][n].x, acc1[1][n].x, acc1[2][n].x,
                                   acc1[3][n].x, c[1][n].x);
                h2[n].y = cell_one(acc1[0][n].y, acc1[1][n].y, acc1[2][n].y,
                                   acc1[3][n].y, c[1][n].y);
            }
            wg_bar(barid, NTHR);   // all pack1 reads done
            float2* hrow = rows + 2 * H * BPC_ + j * BPC_;
#pragma unroll
            for (int n = 0; n < NB; n++) {
                int bp = n * GROUPS + group;
                hrow[bp] = h2[n];
                *reinterpret_cast<float2*>(&bout[j * BATCH + 2 * bp]) = h2[n];
            }
        }

        wg_bar(barid, NTHR);   // h(t) + gout visible
        if (!LAST && wtid == 0) st_rel(fout + t, 1u);
    }
}

// ---------------------------------------------------------------------------
// 128 CTAs x 768 threads:
//  tid<512 (16 warps): stack3 layer (cta>>1), batch half (cta&1), BPC=64
//  tid>=512 (8 warps): cta<64 -> stack2 layer cta; cta in [64,80) -> stack1
//                      pack2; else exit after init
// ---------------------------------------------------------------------------
__global__ void __launch_bounds__(768, 1)
lstm_pipe(const float* l1_Wih0, const float* l1_Whh0, const float* l1_bih0, const float* l1_bhh0,
          const float* l1_Wih,  const float* l1_Whh,  const float* l1_bih,  const float* l1_bhh,
          const float* l2_Wih0, const float* l2_Whh0, const float* l2_bih0, const float* l2_bhh0,
          const float* l2_Wih,  const float* l2_Whh,  const float* l2_bih,  const float* l2_bhh,
          const float* l3_Wih0, const float* l3_Whh0, const float* l3_bih0, const float* l3_bhh0,
          const float* l3_Wih,  const float* l3_Whh,  const float* l3_bih,  const float* l3_bhh)
{
    __shared__ __align__(16) float4 sW0[32 * 16];        // 8KB  s3 weights
    __shared__ __align__(16) float4 sB0[16];
    __shared__ __align__(16) float2 rows0[2 * 16 * 64];  // 16KB s3 rows
    __shared__ __align__(16) float4 sW1[128];            // 2KB  s2 / s1-pack2
    __shared__ __align__(16) float4 sB1[16];
    __shared__ __align__(16) float2 rows1[2048];         // 16KB

    const int tid = threadIdx.x, cta = blockIdx.x;
    const int d = cta >> 1;

    if (tid < 512) {
        fill_s4<16, 8>(sW0, sB0, l3_Wih0, l3_Whh0, l3_bih0, l3_bhh0,
                       l3_Wih, l3_Whh, l3_bih, l3_bhh, d, tid, 512);
    } else {
        const int wtid = tid - 512;
        if (cta < 64) {
            fill_s4<8, 4>(sW1, sB1, l2_Wih0, l2_Whh0, l2_bih0, l2_bhh0,
                          l2_Wih, l2_Whh, l2_bih, l2_bhh, cta, wtid, 256);
        } else if (cta < 80) {
            const int i0 = cta - 64;
            fill_s4<4, 2>(sW1, sB1, l1_Wih0, l1_Whh0, l1_bih0, l1_bhh0,
                          l1_Wih, l1_Whh, l1_bih, l1_bhh, 2 * i0, wtid, 256);
            fill_s4<4, 2>(sW1 + 32, sB1 + 4, l1_Wih0, l1_Whh0, l1_bih0, l1_bhh0,
                          l1_Wih, l1_Whh, l1_bih, l1_bhh, 2 * i0 + 1, wtid, 256);
        }
    }
    __syncthreads();

    if (tid < 512) {
        // ---- stack3: half batch, 512 threads, barid 1 ----
        const int wtid = tid;
        const int s = cta & 1;
        const int q = 80 + d;
        const float* bufin = g_act[q & 1];
        float* bufout = g_act[(q + 1) & 1];
        const unsigned* fin = (d == 0) ? FLAG(79, 0) : FLAG(q - 1, s);
        unsigned* fout = FLAG(q, s);
        const int b0 = s * 128;
        if (d == 0)
            stage_loop<16, 1, 64, 8, 512, false, true, false>(sW0, sB0, rows0, bufin, bufout, fin, fout, b0, wtid, 1);
        else if (d == 63)
            stage_loop<16, 1, 64, 16, 512, false, false, true>(sW0, sB0, rows0, bufin, bufout, fin, fout, b0, wtid, 1);
        else
            stage_loop<16, 1, 64, 16, 512, false, false, false>(sW0, sB0, rows0, bufin, bufout, fin, fout, b0, wtid, 1);
    } else if (cta < 64) {
        // ---- stack2: single layer, full batch, 256 threads, barid 2 ----
        const int wtid = tid - 512;
        const int u = cta, q = 16 + u;
        const float* bufin = g_act[q & 1];
        float* bufout = g_act[(q + 1) & 1];
        const unsigned* fin = FLAG(q - 1, 0);
        unsigned* fout = FLAG(q, 0);
        if (u == 0)
            stage_loop<8, 1, 128, 4, 256, false, true, false>(sW1, sB1, rows1, bufin, bufout, fin, fout, 0, wtid, 2);
        else
            stage_loop<8, 1, 128, 8, 256, false, false, false>(sW1, sB1, rows1, bufin, bufout, fin, fout, 0, wtid, 2);
    } else if (cta < 80) {
        // ---- stack1: pack2, full batch, 256 threads, barid 2 ----
        const int wtid = tid - 512;
        const int i0 = cta - 64, q = i0;
        const float* bufin = g_act[q & 1];
        float* bufout = g_act[(q + 1) & 1];
        const unsigned* fin = FLAG(q > 0 ? q - 1 : 0, 0);
        unsigned* fout = FLAG(q, 0);
        if (i0 == 0)
            stage_loop<4, 2, 128, 2, 256, true, false, false>(sW1, sB1, rows1, bufin, bufout, fin, fout, 0, wtid, 2);
        else
            stage_loop<4, 2, 128, 4, 256, false, false, false>(sW1, sB1, rows1, bufin, bufout, fin, fout, 0, wtid, 2);
    }
}

// ---------------------------------------------------------------------------
// Pre: transpose x -> g_act[0][t][m][b] AND clear all flags (replay-safe).
// Post: ReLU + FC(16->4).
// ---------------------------------------------------------------------------
__global__ void pre_kernel(const float* __restrict__ x) {
    int t = blockIdx.x, b = threadIdx.x;
    float2 v = *reinterpret_cast<const float2*>(&x[((size_t)t * BATCH + b) * 2]);
    g_act[0][(t * 16 + 0) * BATCH + b] = v.x;
    g_act[0][(t * 16 + 1) * BATCH + b] = v.y;
    int idx = t * BATCH + b;
    for (int i = idx; i < NSTAGES * 2 * T_STEPS; i += T_STEPS * BATCH)
        g_flags[i] = 0;
}

__global__ void fc_kernel(const float* __restrict__ fcW, const float* __restrict__ fcb,
                          float* __restrict__ out) {
    int t = blockIdx.x, b = threadIdx.x;
    float v[16];
#pragma unroll
    for (int m = 0; m < 16; m++)
        v[m] = fmaxf(g_act[0][(t * 16 + m) * BATCH + b], 0.f);
#pragma unroll
    for (int q = 0; q < 4; q++) {
        float a = fcb[q];
#pragma unroll
        for (int m = 0; m < 16; m++) a = fmaf(v[m], fcW[q * 16 + m], a);
        out[((size_t)t * BATCH + b) * 4 + q] = a;
    }
}

// ---------------------------------------------------------------------------
extern "C" void kernel_launch(void* const* d_in, const int* in_sizes, int n_in,
                              void* d_out, int out_size) {
#define F(i) ((const float*)d_in[i])
    pre_kernel<<<T_STEPS, BATCH>>>(F(0));
    lstm_pipe<<<128, 768>>>(
        F(1), F(2), F(3), F(4), F(5), F(6), F(7), F(8),
        F(9), F(10), F(11), F(12), F(13), F(14), F(15), F(16),
        F(17), F(18), F(19), F(20), F(21), F(22), F(23), F(24));
    fc_kernel<<<T_STEPS, BATCH>>>(F(25), F(26), (float*)d_out);
#undef F
}

// round 9
// speedup vs baseline: 1.2622x; 1.0939x over previous
#include <cuda_runtime.h>

#define T_STEPS 512
#define BATCH   256
#define NSTAGES 144     // q: s1 0..15, s2 16..79, s3 80..143

// Ping-pong activation buffers, layout [t][feature(16)][batch]
__device__ __align__(16) float g_act[2][T_STEPS * 16 * BATCH];
// Flags [stage][split(2)][t]; cleared by pre_kernel each replay.
__device__ unsigned g_flags[NSTAGES * 2 * T_STEPS];

#define FLAG(q, s) (g_flags + ((size_t)(q) * 2 + (s)) * T_STEPS)

// ---------------------------------------------------------------------------
__device__ __forceinline__ unsigned ld_acq(const unsigned* p) {
    unsigned v;
    asm volatile("ld.acquire.gpu.global.u32 %0, [%1];" : "=r"(v) : "l"(p) : "memory");
    return v;
}
__device__ __forceinline__ void st_rel(unsigned* p, unsigned v) {
    asm volatile("st.release.gpu.global.u32 [%0], %1;" :: "l"(p), "r"(v) : "memory");
}
__device__ __forceinline__ float2 ffma2(float2 a, float2 b, float2 c) {
    float2 d;
    asm("fma.rn.f32x2 %0, %1, %2, %3;"
        : "=l"(reinterpret_cast<unsigned long long&>(d))
        : "l"(reinterpret_cast<unsigned long long&>(a)),
          "l"(reinterpret_cast<unsigned long long&>(b)),
          "l"(reinterpret_cast<unsigned long long&>(c)));
    return d;
}
__device__ __forceinline__ void wg_bar(int id, int nthr) {
    asm volatile("bar.sync %0, %1;" :: "r"(id), "r"(nthr) : "memory");
}

// Fast tanh (MUFU.TANH, sm_75+): 1 MUFU per activation.
__device__ __forceinline__ float tanh_fast(float x) {
    float y;
    asm("tanh.approx.f32 %0, %1;" : "=f"(y) : "f"(x));
    return y;
}

// LSTM nonlinearity via tanh.approx: 5 MUFU + ~8 FMA per value.
// sigmoid(x) = 0.5*tanh(x/2) + 0.5
__device__ __forceinline__ float cell_one(float gi, float gf, float gg, float go,
                                          float& c) {
    float si = fmaf(tanh_fast(0.5f * gi), 0.5f, 0.5f);
    float sf = fmaf(tanh_fast(0.5f * gf), 0.5f, 0.5f);
    float tg = tanh_fast(gg);
    float so = fmaf(tanh_fast(0.5f * go), 0.5f, 0.5f);
    c = fmaf(sf, c, si * tg);
    return so * tanh_fast(c);
}

// ---------------------------------------------------------------------------
// Gate-packed weight fill: W4[k*H + j] = {w_i, w_f, w_g, w_o} for (k, j).
// ---------------------------------------------------------------------------
template<int H, int DIN0>
__device__ void fill_s4(float4* W4, float4* B4,
                        const float* Wih0, const float* Whh0,
                        const float* bih0, const float* bhh0,
                        const float* Wih,  const float* Whh,
                        const float* bih,  const float* bhh,
                        int l, int wtid, int stride) {
    constexpr int G = 4 * H, KM = 2 * H;
    const float* wi = l ? Wih + (size_t)(l - 1) * G * H : Wih0;
    const float* wh = l ? Whh + (size_t)(l - 1) * G * H : Whh0;
    const float* bi = l ? bih + (l - 1) * G : bih0;
    const float* bh = l ? bhh + (l - 1) * G : bhh0;
    const int din = l ? H : DIN0;
    for (int i = wtid; i < KM * H; i += stride) {
        int k = i / H, j = i % H;
        float v[4];
#pragma unroll
        for (int g = 0; g < 4; g++) {
            float w = 0.f;
            if (k < din)     w = wi[(g * H + j) * din + k];
            else if (k >= H) w = wh[(g * H + j) * H + (k - H)];
            v[g] = w;
        }
        W4[i] = make_float4(v[0], v[1], v[2], v[3]);
    }
    for (int jj = wtid; jj < H; jj += stride)
        B4[jj] = make_float4(bi[0 * H + jj] + bh[0 * H + jj],
                             bi[1 * H + jj] + bh[1 * H + jj],
                             bi[2 * H + jj] + bh[2 * H + jj],
                             bi[3 * H + jj] + bh[3 * H + jj]);
}

// ---------------------------------------------------------------------------
// Stage loop. rows: [0,H) x (rows [DSTAGE,H) stay zero), pack-p h at
// [(p+1)H,(p+2)H).  Order per step:
//   P1 pack0 recurrent FMA
//   P2 poll + x LDG + smem commit + bar
//   P3 pack0 x-part FMA + activations + h0 write (+ gout if PACK==1)
//   [PACK==2: bar, pack1 full FMA + act, bar, h1 write + gout]
//   end bar, then flag release
// ---------------------------------------------------------------------------
template<int H, int PACK, int BPC_, int DSTAGE, int NTHR, bool FIRST, bool RELU, bool LAST>
__device__ void stage_loop(const float4* __restrict__ sW, const float4* __restrict__ sB,
                           float2* rows,
                           const float* __restrict__ bufin, float* __restrict__ bufout,
                           const unsigned* fin, unsigned* fout, int b0,
                           int wtid, int barid) {
    constexpr int GROUPS = NTHR / H;
    constexpr int NB = BPC_ / GROUPS;
    constexpr int KM = 2 * H;
    constexpr int QROW = BPC_ / 2;               // float4 slots per feature row
    constexpr int NQ = DSTAGE * QROW;
    constexpr int NLD = (NQ + NTHR - 1) / NTHR;
    const int j = wtid / GROUPS, group = wtid % GROUPS;

    float2 c[PACK][NB];
#pragma unroll
    for (int p = 0; p < PACK; p++)
#pragma unroll
        for (int n = 0; n < NB; n++) c[p][n] = make_float2(0.f, 0.f);

    for (int i = wtid; i < (PACK + 1) * H * BPC_; i += NTHR)
        rows[i] = make_float2(0.f, 0.f);
    wg_bar(barid, NTHR);

    for (int t = 0; t < T_STEPS; t++) {
        // --- P1: pack0 recurrent half (h(t-1) already in smem) ---
        float2 acc[4][NB];
        {
            float4 bv = sB[j];
#pragma unroll
            for (int n = 0; n < NB; n++) {
                acc[0][n] = make_float2(bv.x, bv.x);
                acc[1][n] = make_float2(bv.y, bv.y);
                acc[2][n] = make_float2(bv.z, bv.z);
                acc[3][n] = make_float2(bv.w, bv.w);
            }
        }
#pragma unroll 4
        for (int k = H; k < KM; k++) {
            float4 wv = sW[k * H + j];
            float2 w0 = make_float2(wv.x, wv.x), w1 = make_float2(wv.y, wv.y);
            float2 w2 = make_float2(wv.z, wv.z), w3 = make_float2(wv.w, wv.w);
#pragma unroll
            for (int n = 0; n < NB; n++) {
                float2 v = rows[k * BPC_ + n * GROUPS + group];
                acc[0][n] = ffma2(w0, v, acc[0][n]);
                acc[1][n] = ffma2(w1, v, acc[1][n]);
                acc[2][n] = ffma2(w2, v, acc[2][n]);
                acc[3][n] = ffma2(w3, v, acc[3][n]);
            }
        }

        // --- P2: poll + x loads + commit ---
        if (!FIRST) { const unsigned* f = fin + t; while (ld_acq(f) == 0) { } }
        const float* bin = bufin + (size_t)t * 16 * BATCH + b0;
        float4 pf[NLD];
#pragma unroll
        for (int L = 0; L < NLD; L++) {
            int i = wtid + L * NTHR;
            if (NQ % NTHR == 0 || i < NQ) {
                int m = i / QROW, q4 = i % QROW;
                pf[L] = __ldcg(reinterpret_cast<const float4*>(&bin[m * BATCH + 4 * q4]));
            }
        }
#pragma unroll
        for (int L = 0; L < NLD; L++) {
            int i = wtid + L * NTHR;
            if (NQ % NTHR == 0 || i < NQ) {
                int m = i / QROW, q4 = i % QROW;
                float4 v = pf[L];
                if (RELU) {
                    v.x = fmaxf(v.x, 0.f); v.y = fmaxf(v.y, 0.f);
                    v.z = fmaxf(v.z, 0.f); v.w = fmaxf(v.w, 0.f);
                }
                *reinterpret_cast<float4*>(&rows[m * BPC_ + 2 * q4]) = v;
            }
        }
        wg_bar(barid, NTHR);   // x(t) visible; all P1 h-reads complete

        // --- P3: pack0 x half + activations + h0 write ---
#pragma unroll 4
        for (int k = 0; k < DSTAGE; k++) {
            float4 wv = sW[k * H + j];
            float2 w0 = make_float2(wv.x, wv.x), w1 = make_float2(wv.y, wv.y);
            float2 w2 = make_float2(wv.z, wv.z), w3 = make_float2(wv.w, wv.w);
#pragma unroll
            for (int n = 0; n < NB; n++) {
                float2 v = rows[k * BPC_ + n * GROUPS + group];
                acc[0][n] = ffma2(w0, v, acc[0][n]);
                acc[1][n] = ffma2(w1, v, acc[1][n]);
                acc[2][n] = ffma2(w2, v, acc[2][n]);
                acc[3][n] = ffma2(w3, v, acc[3][n]);
            }
        }
        float* bout = bufout + (size_t)t * 16 * BATCH + b0;
        {
            float2 h2[NB];
#pragma unroll
            for (int n = 0; n < NB; n++) {
                h2[n].x = cell_one(acc[0][n].x, acc[1][n].x, acc[2][n].x,
                                   acc[3][n].x, c[0][n].x);
                h2[n].y = cell_one(acc[0][n].y, acc[1][n].y, acc[2][n].y,
                                   acc[3][n].y, c[0][n].y);
            }
            float2* hrow = rows + H * BPC_ + j * BPC_;
#pragma unroll
            for (int n = 0; n < NB; n++) {
                int bp = n * GROUPS + group;
                hrow[bp] = h2[n];
                if (PACK == 1)
                    *reinterpret_cast<float2*>(&bout[j * BATCH + 2 * bp]) = h2[n];
            }
        }

        if (PACK > 1) {
            wg_bar(barid, NTHR);   // h0(t) visible
            float2 acc1[4][NB];
            {
                float4 bv = sB[H + j];
#pragma unroll
                for (int n = 0; n < NB; n++) {
                    acc1[0][n] = make_float2(bv.x, bv.x);
                    acc1[1][n] = make_float2(bv.y, bv.y);
                    acc1[2][n] = make_float2(bv.z, bv.z);
                    acc1[3][n] = make_float2(bv.w, bv.w);
                }
            }
#pragma unroll 4
            for (int k = 0; k < KM; k++) {
                float4 wv = sW[KM * H + k * H + j];
                float2 w0 = make_float2(wv.x, wv.x), w1 = make_float2(wv.y, wv.y);
                float2 w2 = make_float2(wv.z, wv.z), w3 = make_float2(wv.w, wv.w);
#pragma unroll
                for (int n = 0; n < NB; n++) {
                    float2 v = rows[(H + k) * BPC_ + n * GROUPS + group];
                    acc1[0][n] = ffma2(w0, v, acc1[0][n]);
                    acc1[1][n] = ffma2(w1, v, acc1[1][n]);
                    acc1[2][n] = ffma2(w2, v, acc1[2][n]);
                    acc1[3][n] = ffma2(w3, v, acc1[3][n]);
                }
            }
            float2 h2[NB];
#pragma unroll
            for (int n = 0; n < NB; n++) {
                h2[n].x = cell_one(acc1[0][n].x, acc1[1][n].x, acc1[2][n].x,
                                   acc1[3][n].x, c[1][n].x);
                h2[n].y = cell_one(acc1[0][n].y, acc1[1][n].y, acc1[2][n].y,
                                   acc1[3][n].y, c[1][n].y);
            }
            wg_bar(barid, NTHR);   // all pack1 reads done
            float2* hrow = rows + 2 * H * BPC_ + j * BPC_;
#pragma unroll
            for (int n = 0; n < NB; n++) {
                int bp = n * GROUPS + group;
                hrow[bp] = h2[n];
                *reinterpret_cast<float2*>(&bout[j * BATCH + 2 * bp]) = h2[n];
            }
        }

        wg_bar(barid, NTHR);   // h(t) + gout visible
        if (!LAST && wtid == 0) st_rel(fout + t, 1u);
    }
}

// ---------------------------------------------------------------------------
// 128 CTAs x 768 threads:
//  tid<512 (16 warps): stack3 layer (cta>>1), batch half (cta&1), BPC=64
//  tid>=512 (8 warps): cta<64 -> stack2 layer cta; cta in [64,80) -> stack1
//                      pack2; else exit after init
// ---------------------------------------------------------------------------
__global__ void __launch_bounds__(768, 1)
lstm_pipe(const float* l1_Wih0, const float* l1_Whh0, const float* l1_bih0, const float* l1_bhh0,
          const float* l1_Wih,  const float* l1_Whh,  const float* l1_bih,  const float* l1_bhh,
          const float* l2_Wih0, const float* l2_Whh0, const float* l2_bih0, const float* l2_bhh0,
          const float* l2_Wih,  const float* l2_Whh,  const float* l2_bih,  const float* l2_bhh,
          const float* l3_Wih0, const float* l3_Whh0, const float* l3_bih0, const float* l3_bhh0,
          const float* l3_Wih,  const float* l3_Whh,  const float* l3_bih,  const float* l3_bhh)
{
    __shared__ __align__(16) float4 sW0[32 * 16];        // 8KB  s3 weights
    __shared__ __align__(16) float4 sB0[16];
    __shared__ __align__(16) float2 rows0[2 * 16 * 64];  // 16KB s3 rows
    __shared__ __align__(16) float4 sW1[128];            // 2KB  s2 / s1-pack2
    __shared__ __align__(16) float4 sB1[16];
    __shared__ __align__(16) float2 rows1[2048];         // 16KB

    const int tid = threadIdx.x, cta = blockIdx.x;
    const int d = cta >> 1;

    if (tid < 512) {
        fill_s4<16, 8>(sW0, sB0, l3_Wih0, l3_Whh0, l3_bih0, l3_bhh0,
                       l3_Wih, l3_Whh, l3_bih, l3_bhh, d, tid, 512);
    } else {
        const int wtid = tid - 512;
        if (cta < 64) {
            fill_s4<8, 4>(sW1, sB1, l2_Wih0, l2_Whh0, l2_bih0, l2_bhh0,
                          l2_Wih, l2_Whh, l2_bih, l2_bhh, cta, wtid, 256);
        } else if (cta < 80) {
            const int i0 = cta - 64;
            fill_s4<4, 2>(sW1, sB1, l1_Wih0, l1_Whh0, l1_bih0, l1_bhh0,
                          l1_Wih, l1_Whh, l1_bih, l1_bhh, 2 * i0, wtid, 256);
            fill_s4<4, 2>(sW1 + 32, sB1 + 4, l1_Wih0, l1_Whh0, l1_bih0, l1_bhh0,
                          l1_Wih, l1_Whh, l1_bih, l1_bhh, 2 * i0 + 1, wtid, 256);
        }
    }
    __syncthreads();

    if (tid < 512) {
        // ---- stack3: half batch, 512 threads, barid 1 ----
        const int wtid = tid;
        const int s = cta & 1;
        const int q = 80 + d;
        const float* bufin = g_act[q & 1];
        float* bufout = g_act[(q + 1) & 1];
        const unsigned* fin = (d == 0) ? FLAG(79, 0) : FLAG(q - 1, s);
        unsigned* fout = FLAG(q, s);
        const int b0 = s * 128;
        if (d == 0)
            stage_loop<16, 1, 64, 8, 512, false, true, false>(sW0, sB0, rows0, bufin, bufout, fin, fout, b0, wtid, 1);
        else if (d == 63)
            stage_loop<16, 1, 64, 16, 512, false, false, true>(sW0, sB0, rows0, bufin, bufout, fin, fout, b0, wtid, 1);
        else
            stage_loop<16, 1, 64, 16, 512, false, false, false>(sW0, sB0, rows0, bufin, bufout, fin, fout, b0, wtid, 1);
    } else if (cta < 64) {
        // ---- stack2: single layer, full batch, 256 threads, barid 2 ----
        const int wtid = tid - 512;
        const int u = cta, q = 16 + u;
        const float* bufin = g_act[q & 1];
        float* bufout = g_act[(q + 1) & 1];
        const unsigned* fin = FLAG(q - 1, 0);
        unsigned* fout = FLAG(q, 0);
        if (u == 0)
            stage_loop<8, 1, 128, 4, 256, false, true, false>(sW1, sB1, rows1, bufin, bufout, fin, fout, 0, wtid, 2);
        else
            stage_loop<8, 1, 128, 8, 256, false, false, false>(sW1, sB1, rows1, bufin, bufout, fin, fout, 0, wtid, 2);
    } else if (cta < 80) {
        // ---- stack1: pack2, full batch, 256 threads, barid 2 ----
        const int wtid = tid - 512;
        const int i0 = cta - 64, q = i0;
        const float* bufin = g_act[q & 1];
        float* bufout = g_act[(q + 1) & 1];
        const unsigned* fin = FLAG(q > 0 ? q - 1 : 0, 0);
        unsigned* fout = FLAG(q, 0);
        if (i0 == 0)
            stage_loop<4, 2, 128, 2, 256, true, false, false>(sW1, sB1, rows1, bufin, bufout, fin, fout, 0, wtid, 2);
        else
            stage_loop<4, 2, 128, 4, 256, false, false, false>(sW1, sB1, rows1, bufin, bufout, fin, fout, 0, wtid, 2);
    }
}

// ---------------------------------------------------------------------------
// Pre: transpose x -> g_act[0][t][m][b] AND clear all flags (replay-safe).
// Post: ReLU + FC(16->4).
// ---------------------------------------------------------------------------
__global__ void pre_kernel(const float* __restrict__ x) {
    int t = blockIdx.x, b = threadIdx.x;
    float2 v = *reinterpret_cast<const float2*>(&x[((size_t)t * BATCH + b) * 2]);
    g_act[0][(t * 16 + 0) * BATCH + b] = v.x;
    g_act[0][(t * 16 + 1) * BATCH + b] = v.y;
    int idx = t * BATCH + b;
    for (int i = idx; i < NSTAGES * 2 * T_STEPS; i += T_STEPS * BATCH)
        g_flags[i] = 0;
}

__global__ void fc_kernel(const float* __restrict__ fcW, const float* __restrict__ fcb,
                          float* __restrict__ out) {
    int t = blockIdx.x, b = threadIdx.x;
    float v[16];
#pragma unroll
    for (int m = 0; m < 16; m++)
        v[m] = fmaxf(g_act[0][(t * 16 + m) * BATCH + b], 0.f);
#pragma unroll
    for (int q = 0; q < 4; q++) {
        float a = fcb[q];
#pragma unroll
        for (int m = 0; m < 16; m++) a = fmaf(v[m], fcW[q * 16 + m], a);
        out[((size_t)t * BATCH + b) * 4 + q] = a;
    }
}

// ---------------------------------------------------------------------------
extern "C" void kernel_launch(void* const* d_in, const int* in_sizes, int n_in,
                              void* d_out, int out_size) {
#define F(i) ((const float*)d_in[i])
    pre_kernel<<<T_STEPS, BATCH>>>(F(0));
    lstm_pipe<<<128, 768>>>(
        F(1), F(2), F(3), F(4), F(5), F(6), F(7), F(8),
        F(9), F(10), F(11), F(12), F(13), F(14), F(15), F(16),
        F(17), F(18), F(19), F(20), F(21), F(22), F(23), F(24));
    fc_kernel<<<T_STEPS, BATCH>>>(F(25), F(26), (float*)d_out);
#undef F
}

// round 10
// speedup vs baseline: 1.5565x; 1.2332x over previous
#include <cuda_runtime.h>

#define T_STEPS 512
#define BATCH   256
#define NSTAGES 144     // q: s1 0..15, s2 16..79, s3 80..143

// Ping-pong activation buffers, layout [t][feature(16)][batch]
__device__ __align__(16) float g_act[2][T_STEPS * 16 * BATCH];
// Flags [stage][split(2)][t]; cleared by pre_kernel each replay.
__device__ unsigned g_flags[NSTAGES * 2 * T_STEPS];

#define FLAG(q, s) (g_flags + ((size_t)(q) * 2 + (s)) * T_STEPS)

// ---------------------------------------------------------------------------
__device__ __forceinline__ unsigned ld_acq(const unsigned* p) {
    unsigned v;
    asm volatile("ld.acquire.gpu.global.u32 %0, [%1];" : "=r"(v) : "l"(p) : "memory");
    return v;
}
__device__ __forceinline__ void st_rel(unsigned* p, unsigned v) {
    asm volatile("st.release.gpu.global.u32 [%0], %1;" :: "l"(p), "r"(v) : "memory");
}
__device__ __forceinline__ float2 ffma2(float2 a, float2 b, float2 c) {
    float2 d;
    asm("fma.rn.f32x2 %0, %1, %2, %3;"
        : "=l"(reinterpret_cast<unsigned long long&>(d))
        : "l"(reinterpret_cast<unsigned long long&>(a)),
          "l"(reinterpret_cast<unsigned long long&>(b)),
          "l"(reinterpret_cast<unsigned long long&>(c)));
    return d;
}
__device__ __forceinline__ void wg_bar(int id, int nthr) {
    asm volatile("bar.sync %0, %1;" :: "r"(id), "r"(nthr) : "memory");
}

// Fast tanh (MUFU.TANH): 1 MUFU per activation.
__device__ __forceinline__ float tanh_fast(float x) {
    float y;
    asm("tanh.approx.f32 %0, %1;" : "=f"(y) : "f"(x));
    return y;
}

// LSTM nonlinearity via tanh.approx: 5 MUFU + ~8 FMA per value.
__device__ __forceinline__ float cell_one(float gi, float gf, float gg, float go,
                                          float& c) {
    float si = fmaf(tanh_fast(0.5f * gi), 0.5f, 0.5f);
    float sf = fmaf(tanh_fast(0.5f * gf), 0.5f, 0.5f);
    float tg = tanh_fast(gg);
    float so = fmaf(tanh_fast(0.5f * go), 0.5f, 0.5f);
    c = fmaf(sf, c, si * tg);
    return so * tanh_fast(c);
}

// ---------------------------------------------------------------------------
// Gate-packed weight fill: W4[k*H + j] = {w_i, w_f, w_g, w_o} for (k, j).
// ---------------------------------------------------------------------------
template<int H, int DIN0>
__device__ void fill_s4(float4* W4, float4* B4,
                        const float* Wih0, const float* Whh0,
                        const float* bih0, const float* bhh0,
                        const float* Wih,  const float* Whh,
                        const float* bih,  const float* bhh,
                        int l, int wtid, int stride) {
    constexpr int G = 4 * H, KM = 2 * H;
    const float* wi = l ? Wih + (size_t)(l - 1) * G * H : Wih0;
    const float* wh = l ? Whh + (size_t)(l - 1) * G * H : Whh0;
    const float* bi = l ? bih + (l - 1) * G : bih0;
    const float* bh = l ? bhh + (l - 1) * G : bhh0;
    const int din = l ? H : DIN0;
    for (int i = wtid; i < KM * H; i += stride) {
        int k = i / H, j = i % H;
        float v[4];
#pragma unroll
        for (int g = 0; g < 4; g++) {
            float w = 0.f;
            if (k < din)     w = wi[(g * H + j) * din + k];
            else if (k >= H) w = wh[(g * H + j) * H + (k - H)];
            v[g] = w;
        }
        W4[i] = make_float4(v[0], v[1], v[2], v[3]);
    }
    for (int jj = wtid; jj < H; jj += stride)
        B4[jj] = make_float4(bi[0 * H + jj] + bh[0 * H + jj],
                             bi[1 * H + jj] + bh[1 * H + jj],
                             bi[2 * H + jj] + bh[2 * H + jj],
                             bi[3 * H + jj] + bh[3 * H + jj]);
}

// ---------------------------------------------------------------------------
// Stage loop. rows: [0,H) x (rows [DSTAGE,H) stay zero), pack-p h at
// [(p+1)H,(p+2)H).  Per step:
//   P1 pack0 recurrent FMA; P2 poll + x LDG + commit + bar;
//   P3 pack0 x FMA + act + h0 write (+gout if PACK==1);
//   [PACK==2: bar, pack1 FMA + act, bar, h1 write + gout]
//   end bar, flag release.
// ---------------------------------------------------------------------------
template<int H, int PACK, int BPC_, int DSTAGE, int NTHR, bool FIRST, bool RELU, bool LAST>
__device__ void stage_loop(const float4* __restrict__ sW, const float4* __restrict__ sB,
                           float2* rows,
                           const float* __restrict__ bufin, float* __restrict__ bufout,
                           const unsigned* fin, unsigned* fout, int b0,
                           int wtid, int barid) {
    constexpr int GROUPS = NTHR / H;
    constexpr int NB = BPC_ / GROUPS;
    constexpr int KM = 2 * H;
    constexpr int QROW = BPC_ / 2;               // float4 slots per feature row
    constexpr int NQ = DSTAGE * QROW;
    constexpr int NLD = (NQ + NTHR - 1) / NTHR;
    const int j = wtid / GROUPS, group = wtid % GROUPS;

    float2 c[PACK][NB];
#pragma unroll
    for (int p = 0; p < PACK; p++)
#pragma unroll
        for (int n = 0; n < NB; n++) c[p][n] = make_float2(0.f, 0.f);

    for (int i = wtid; i < (PACK + 1) * H * BPC_; i += NTHR)
        rows[i] = make_float2(0.f, 0.f);
    wg_bar(barid, NTHR);

    for (int t = 0; t < T_STEPS; t++) {
        // --- P1: pack0 recurrent half ---
        float2 acc[4][NB];
        {
            float4 bv = sB[j];
#pragma unroll
            for (int n = 0; n < NB; n++) {
                acc[0][n] = make_float2(bv.x, bv.x);
                acc[1][n] = make_float2(bv.y, bv.y);
                acc[2][n] = make_float2(bv.z, bv.z);
                acc[3][n] = make_float2(bv.w, bv.w);
            }
        }
#pragma unroll 4
        for (int k = H; k < KM; k++) {
            float4 wv = sW[k * H + j];
            float2 w0 = make_float2(wv.x, wv.x), w1 = make_float2(wv.y, wv.y);
            float2 w2 = make_float2(wv.z, wv.z), w3 = make_float2(wv.w, wv.w);
#pragma unroll
            for (int n = 0; n < NB; n++) {
                float2 v = rows[k * BPC_ + n * GROUPS + group];
                acc[0][n] = ffma2(w0, v, acc[0][n]);
                acc[1][n] = ffma2(w1, v, acc[1][n]);
                acc[2][n] = ffma2(w2, v, acc[2][n]);
                acc[3][n] = ffma2(w3, v, acc[3][n]);
            }
        }

        // --- P2: poll + x loads + commit ---
        if (!FIRST) { const unsigned* f = fin + t; while (ld_acq(f) == 0) { } }
        const float* bin = bufin + (size_t)t * 16 * BATCH + b0;
        float4 pf[NLD];
#pragma unroll
        for (int L = 0; L < NLD; L++) {
            int i = wtid + L * NTHR;
            if (NQ % NTHR == 0 || i < NQ) {
                int m = i / QROW, q4 = i % QROW;
                pf[L] = __ldcg(reinterpret_cast<const float4*>(&bin[m * BATCH + 4 * q4]));
            }
        }
#pragma unroll
        for (int L = 0; L < NLD; L++) {
            int i = wtid + L * NTHR;
            if (NQ % NTHR == 0 || i < NQ) {
                int m = i / QROW, q4 = i % QROW;
                float4 v = pf[L];
                if (RELU) {
                    v.x = fmaxf(v.x, 0.f); v.y = fmaxf(v.y, 0.f);
                    v.z = fmaxf(v.z, 0.f); v.w = fmaxf(v.w, 0.f);
                }
                *reinterpret_cast<float4*>(&rows[m * BPC_ + 2 * q4]) = v;
            }
        }
        wg_bar(barid, NTHR);   // x(t) visible; all P1 h-reads complete

        // --- P3: pack0 x half + activations + h0 write ---
#pragma unroll 4
        for (int k = 0; k < DSTAGE; k++) {
            float4 wv = sW[k * H + j];
            float2 w0 = make_float2(wv.x, wv.x), w1 = make_float2(wv.y, wv.y);
            float2 w2 = make_float2(wv.z, wv.z), w3 = make_float2(wv.w, wv.w);
#pragma unroll
            for (int n = 0; n < NB; n++) {
                float2 v = rows[k * BPC_ + n * GROUPS + group];
                acc[0][n] = ffma2(w0, v, acc[0][n]);
                acc[1][n] = ffma2(w1, v, acc[1][n]);
                acc[2][n] = ffma2(w2, v, acc[2][n]);
                acc[3][n] = ffma2(w3, v, acc[3][n]);
            }
        }
        float* bout = bufout + (size_t)t * 16 * BATCH + b0;
        {
            float2 h2[NB];
#pragma unroll
            for (int n = 0; n < NB; n++) {
                h2[n].x = cell_one(acc[0][n].x, acc[1][n].x, acc[2][n].x,
                                   acc[3][n].x, c[0][n].x);
                h2[n].y = cell_one(acc[0][n].y, acc[1][n].y, acc[2][n].y,
                                   acc[3][n].y, c[0][n].y);
            }
            float2* hrow = rows + H * BPC_ + j * BPC_;
#pragma unroll
            for (int n = 0; n < NB; n++) {
                int bp = n * GROUPS + group;
                hrow[bp] = h2[n];
                if (PACK == 1)
                    *reinterpret_cast<float2*>(&bout[j * BATCH + 2 * bp]) = h2[n];
            }
        }

        if (PACK > 1) {
            wg_bar(barid, NTHR);   // h0(t) visible
            float2 acc1[4][NB];
            {
                float4 bv = sB[H + j];
#pragma unroll
                for (int n = 0; n < NB; n++) {
                    acc1[0][n] = make_float2(bv.x, bv.x);
                    acc1[1][n] = make_float2(bv.y, bv.y);
                    acc1[2][n] = make_float2(bv.z, bv.z);
                    acc1[3][n] = make_float2(bv.w, bv.w);
                }
            }
#pragma unroll 4
            for (int k = 0; k < KM; k++) {
                float4 wv = sW[KM * H + k * H + j];
                float2 w0 = make_float2(wv.x, wv.x), w1 = make_float2(wv.y, wv.y);
                float2 w2 = make_float2(wv.z, wv.z), w3 = make_float2(wv.w, wv.w);
#pragma unroll
                for (int n = 0; n < NB; n++) {
                    float2 v = rows[(H + k) * BPC_ + n * GROUPS + group];
                    acc1[0][n] = ffma2(w0, v, acc1[0][n]);
                    acc1[1][n] = ffma2(w1, v, acc1[1][n]);
                    acc1[2][n] = ffma2(w2, v, acc1[2][n]);
                    acc1[3][n] = ffma2(w3, v, acc1[3][n]);
                }
            }
            float2 h2[NB];
#pragma unroll
            for (int n = 0; n < NB; n++) {
                h2[n].x = cell_one(acc1[0][n].x, acc1[1][n].x, acc1[2][n].x,
                                   acc1[3][n].x, c[1][n].x);
                h2[n].y = cell_one(acc1[0][n].y, acc1[1][n].y, acc1[2][n].y,
                                   acc1[3][n].y, c[1][n].y);
            }
            wg_bar(barid, NTHR);   // all pack1 reads done
            float2* hrow = rows + 2 * H * BPC_ + j * BPC_;
#pragma unroll
            for (int n = 0; n < NB; n++) {
                int bp = n * GROUPS + group;
                hrow[bp] = h2[n];
                *reinterpret_cast<float2*>(&bout[j * BATCH + 2 * bp]) = h2[n];
            }
        }

        wg_bar(barid, NTHR);   // h(t) + gout visible
        if (!LAST && wtid == 0) st_rel(fout + t, 1u);
    }
}

// ---------------------------------------------------------------------------
// 144 CTAs x 768 threads, one per SM:
//  CTA 0..127:  tid<512: s3 layer cta>>1, batch half cta&1 (BPC=64)
//               tid>=512: s2 layer cta>>1, batch half cta&1 (BPC=64)
//  CTA 128..143: tid<256: s1 pack2 unit cta-128, full batch; else exit
// ---------------------------------------------------------------------------
__global__ void __launch_bounds__(768, 1)
lstm_pipe(const float* l1_Wih0, const float* l1_Whh0, const float* l1_bih0, const float* l1_bhh0,
          const float* l1_Wih,  const float* l1_Whh,  const float* l1_bih,  const float* l1_bhh,
          const float* l2_Wih0, const float* l2_Whh0, const float* l2_bih0, const float* l2_bhh0,
          const float* l2_Wih,  const float* l2_Whh,  const float* l2_bih,  const float* l2_bhh,
          const float* l3_Wih0, const float* l3_Whh0, const float* l3_bih0, const float* l3_bhh0,
          const float* l3_Wih,  const float* l3_Whh,  const float* l3_bih,  const float* l3_bhh)
{
    __shared__ __align__(16) float4 sW0[32 * 16];        // 8KB  s3 weights
    __shared__ __align__(16) float4 sB0[16];
    __shared__ __align__(16) float2 rows0[2 * 16 * 64];  // 16KB s3 rows
    __shared__ __align__(16) float4 sW1[128];            // 2KB  s2 / s1-pack2
    __shared__ __align__(16) float4 sB1[16];
    __shared__ __align__(16) float2 rows1[2048];         // 16KB (s2-half uses 1/4)

    const int tid = threadIdx.x, cta = blockIdx.x;

    if (cta < 128) {
        const int d = cta >> 1;
        if (tid < 512) {
            fill_s4<16, 8>(sW0, sB0, l3_Wih0, l3_Whh0, l3_bih0, l3_bhh0,
                           l3_Wih, l3_Whh, l3_bih, l3_bhh, d, tid, 512);
        } else {
            fill_s4<8, 4>(sW1, sB1, l2_Wih0, l2_Whh0, l2_bih0, l2_bhh0,
                          l2_Wih, l2_Whh, l2_bih, l2_bhh, d, tid - 512, 256);
        }
    } else if (tid < 256) {
        const int i0 = cta - 128;
        fill_s4<4, 2>(sW1, sB1, l1_Wih0, l1_Whh0, l1_bih0, l1_bhh0,
                      l1_Wih, l1_Whh, l1_bih, l1_bhh, 2 * i0, tid, 256);
        fill_s4<4, 2>(sW1 + 32, sB1 + 4, l1_Wih0, l1_Whh0, l1_bih0, l1_bhh0,
                      l1_Wih, l1_Whh, l1_bih, l1_bhh, 2 * i0 + 1, tid, 256);
    }
    __syncthreads();

    if (cta < 128) {
        const int d = cta >> 1, s = cta & 1;
        const int b0 = s * 128;
        if (tid < 512) {
            // ---- s3 half-batch, 512 threads, barid 1 ----
            const int q = 80 + d;
            const float* bufin = g_act[q & 1];
            float* bufout = g_act[(q + 1) & 1];
            const unsigned* fin = (d == 0) ? FLAG(79, s) : FLAG(q - 1, s);
            unsigned* fout = FLAG(q, s);
            if (d == 0)
                stage_loop<16, 1, 64, 8, 512, false, true, false>(sW0, sB0, rows0, bufin, bufout, fin, fout, b0, tid, 1);
            else if (d == 63)
                stage_loop<16, 1, 64, 16, 512, false, false, true>(sW0, sB0, rows0, bufin, bufout, fin, fout, b0, tid, 1);
            else
                stage_loop<16, 1, 64, 16, 512, false, false, false>(sW0, sB0, rows0, bufin, bufout, fin, fout, b0, tid, 1);
        } else {
            // ---- s2 half-batch, 256 threads, barid 2 ----
            const int wtid = tid - 512;
            const int q = 16 + d;
            const float* bufin = g_act[q & 1];
            float* bufout = g_act[(q + 1) & 1];
            const unsigned* fin = (d == 0) ? FLAG(15, 0) : FLAG(q - 1, s);
            unsigned* fout = FLAG(q, s);
            if (d == 0)
                stage_loop<8, 1, 64, 4, 256, false, true, false>(sW1, sB1, rows1, bufin, bufout, fin, fout, b0, wtid, 2);
            else
                stage_loop<8, 1, 64, 8, 256, false, false, false>(sW1, sB1, rows1, bufin, bufout, fin, fout, b0, wtid, 2);
        }
    } else if (tid < 256) {
        // ---- s1 pack2, full batch, 256 threads, barid 1 ----
        const int i0 = cta - 128, q = i0;
        const float* bufin = g_act[q & 1];
        float* bufout = g_act[(q + 1) & 1];
        const unsigned* fin = FLAG(q > 0 ? q - 1 : 0, 0);
        unsigned* fout = FLAG(q, 0);
        if (i0 == 0)
            stage_loop<4, 2, 128, 2, 256, true, false, false>(sW1, sB1, rows1, bufin, bufout, fin, fout, 0, tid, 1);
        else
            stage_loop<4, 2, 128, 4, 256, false, false, false>(sW1, sB1, rows1, bufin, bufout, fin, fout, 0, tid, 1);
    }
}

// ---------------------------------------------------------------------------
// Pre: transpose x -> g_act[0][t][m][b] AND clear all flags (replay-safe).
// Post: ReLU + FC(16->4).
// ---------------------------------------------------------------------------
__global__ void pre_kernel(const float* __restrict__ x) {
    int t = blockIdx.x, b = threadIdx.x;
    float2 v = *reinterpret_cast<const float2*>(&x[((size_t)t * BATCH + b) * 2]);
    g_act[0][(t * 16 + 0) * BATCH + b] = v.x;
    g_act[0][(t * 16 + 1) * BATCH + b] = v.y;
    int idx = t * BATCH + b;
    for (int i = idx; i < NSTAGES * 2 * T_STEPS; i += T_STEPS * BATCH)
        g_flags[i] = 0;
}

__global__ void fc_kernel(const float* __restrict__ fcW, const float* __restrict__ fcb,
                          float* __restrict__ out) {
    int t = blockIdx.x, b = threadIdx.x;
    float v[16];
#pragma unroll
    for (int m = 0; m < 16; m++)
        v[m] = fmaxf(g_act[0][(t * 16 + m) * BATCH + b], 0.f);
#pragma unroll
    for (int q = 0; q < 4; q++) {
        float a = fcb[q];
#pragma unroll
        for (int m = 0; m < 16; m++) a = fmaf(v[m], fcW[q * 16 + m], a);
        out[((size_t)t * BATCH + b) * 4 + q] = a;
    }
}

// ---------------------------------------------------------------------------
extern "C" void kernel_launch(void* const* d_in, const int* in_sizes, int n_in,
                              void* d_out, int out_size) {
#define F(i) ((const float*)d_in[i])
    pre_kernel<<<T_STEPS, BATCH>>>(F(0));
    lstm_pipe<<<144, 768>>>(
        F(1), F(2), F(3), F(4), F(5), F(6), F(7), F(8),
        F(9), F(10), F(11), F(12), F(13), F(14), F(15), F(16),
        F(17), F(18), F(19), F(20), F(21), F(22), F(23), F(24));
    fc_kernel<<<T_STEPS, BATCH>>>(F(25), F(26), (float*)d_out);
#undef F
}

// round 11
// speedup vs baseline: 1.6057x; 1.0316x over previous
#include <cuda_runtime.h>

#define T_STEPS 512
#define BATCH   256
#define NSTAGES 144     // q: s1 0..15, s2 16..79, s3 80..143

// Ping-pong activation buffers, layout [t][feature(16)][batch]
__device__ __align__(16) float g_act[2][T_STEPS * 16 * BATCH];
// Flags [stage][split(2)][t]; cleared by pre_kernel each replay.
__device__ unsigned g_flags[NSTAGES * 2 * T_STEPS];

#define FLAG(q, s) (g_flags + ((size_t)(q) * 2 + (s)) * T_STEPS)

// ---------------------------------------------------------------------------
__device__ __forceinline__ unsigned ld_acq(const unsigned* p) {
    unsigned v;
    asm volatile("ld.acquire.gpu.global.u32 %0, [%1];" : "=r"(v) : "l"(p) : "memory");
    return v;
}
__device__ __forceinline__ void st_rel(unsigned* p, unsigned v) {
    asm volatile("st.release.gpu.global.u32 [%0], %1;" :: "l"(p), "r"(v) : "memory");
}
__device__ __forceinline__ float2 ffma2(float2 a, float2 b, float2 c) {
    float2 d;
    asm("fma.rn.f32x2 %0, %1, %2, %3;"
        : "=l"(reinterpret_cast<unsigned long long&>(d))
        : "l"(reinterpret_cast<unsigned long long&>(a)),
          "l"(reinterpret_cast<unsigned long long&>(b)),
          "l"(reinterpret_cast<unsigned long long&>(c)));
    return d;
}
__device__ __forceinline__ void wg_bar(int id, int nthr) {
    asm volatile("bar.sync %0, %1;" :: "r"(id), "r"(nthr) : "memory");
}
__device__ __forceinline__ float tanh_fast(float x) {
    float y;
    asm("tanh.approx.f32 %0, %1;" : "=f"(y) : "f"(x));
    return y;
}
// LSTM nonlinearity via tanh.approx: 5 MUFU + ~8 FMA per value.
__device__ __forceinline__ float cell_one(float gi, float gf, float gg, float go,
                                          float& c) {
    float si = fmaf(tanh_fast(0.5f * gi), 0.5f, 0.5f);
    float sf = fmaf(tanh_fast(0.5f * gf), 0.5f, 0.5f);
    float tg = tanh_fast(gg);
    float so = fmaf(tanh_fast(0.5f * go), 0.5f, 0.5f);
    c = fmaf(sf, c, si * tg);
    return so * tanh_fast(c);
}

// ---------------------------------------------------------------------------
// Gate-packed weight fill: W4[k*H + j] = {w_i, w_f, w_g, w_o} for (k, j).
// ---------------------------------------------------------------------------
template<int H, int DIN0>
__device__ void fill_s4(float4* W4, float4* B4,
                        const float* Wih0, const float* Whh0,
                        const float* bih0, const float* bhh0,
                        const float* Wih,  const float* Whh,
                        const float* bih,  const float* bhh,
                        int l, int wtid, int stride) {
    constexpr int G = 4 * H, KM = 2 * H;
    const float* wi = l ? Wih + (size_t)(l - 1) * G * H : Wih0;
    const float* wh = l ? Whh + (size_t)(l - 1) * G * H : Whh0;
    const float* bi = l ? bih + (l - 1) * G : bih0;
    const float* bh = l ? bhh + (l - 1) * G : bhh0;
    const int din = l ? H : DIN0;
    for (int i = wtid; i < KM * H; i += stride) {
        int k = i / H, j = i % H;
        float v[4];
#pragma unroll
        for (int g = 0; g < 4; g++) {
            float w = 0.f;
            if (k < din)     w = wi[(g * H + j) * din + k];
            else if (k >= H) w = wh[(g * H + j) * H + (k - H)];
            v[g] = w;
        }
        W4[i] = make_float4(v[0], v[1], v[2], v[3]);
    }
    for (int jj = wtid; jj < H; jj += stride)
        B4[jj] = make_float4(bi[0 * H + jj] + bh[0 * H + jj],
                             bi[1 * H + jj] + bh[1 * H + jj],
                             bi[2 * H + jj] + bh[2 * H + jj],
                             bi[3 * H + jj] + bh[3 * H + jj]);
}

// ---------------------------------------------------------------------------
// Stage loop with JB=2-style register blocking and NB=2 adjacent batch pairs.
// Thread (jj, group) computes gates for j in {jj*JB..jj*JB+JB-1} and batch
// pairs bp in {group*NB..group*NB+NB-1}.  Activation float4 loads are reused
// across JB j's; weight LDS.128 is warp-uniform (broadcast).
// rows: [0,H) x rows (rows [DSTAGE,H) stay zero), pack-p h at [(p+1)H,(p+2)H).
// ---------------------------------------------------------------------------
template<int H, int JB, int PACK, int BPC_, int DSTAGE, int NTHR, bool FIRST, bool RELU, bool LAST>
__device__ void stage_loop(const float4* __restrict__ sW, const float4* __restrict__ sB,
                           float2* rows,
                           const float* __restrict__ bufin, float* __restrict__ bufout,
                           const unsigned* fin, unsigned* fout, int b0,
                           int wtid, int barid) {
    constexpr int NJJ = H / JB;
    constexpr int GROUPS = NTHR / NJJ;
    constexpr int NB = BPC_ / GROUPS;            // == 2 in all configs
    static_assert(NB == 2, "mapping assumes NB==2");
    constexpr int KM = 2 * H;
    constexpr int QROW = BPC_ / 2;               // float4 slots per feature row
    constexpr int NQ = DSTAGE * QROW;
    constexpr int NLD = (NQ + NTHR - 1) / NTHR;
    const int jj = wtid / GROUPS, group = wtid % GROUPS;

    float2 c[PACK][JB][NB];
#pragma unroll
    for (int p = 0; p < PACK; p++)
#pragma unroll
        for (int jb = 0; jb < JB; jb++)
#pragma unroll
            for (int n = 0; n < NB; n++) c[p][jb][n] = make_float2(0.f, 0.f);

    for (int i = wtid; i < (PACK + 1) * H * BPC_; i += NTHR)
        rows[i] = make_float2(0.f, 0.f);
    wg_bar(barid, NTHR);

    for (int t = 0; t < T_STEPS; t++) {
        // --- P1: pack0 recurrent half ---
        float2 acc[4][JB][NB];
#pragma unroll
        for (int jb = 0; jb < JB; jb++) {
            float4 bv = sB[jj * JB + jb];
#pragma unroll
            for (int n = 0; n < NB; n++) {
                acc[0][jb][n] = make_float2(bv.x, bv.x);
                acc[1][jb][n] = make_float2(bv.y, bv.y);
                acc[2][jb][n] = make_float2(bv.z, bv.z);
                acc[3][jb][n] = make_float2(bv.w, bv.w);
            }
        }
#pragma unroll 4
        for (int k = H; k < KM; k++) {
            float4 vv = *reinterpret_cast<const float4*>(&rows[k * BPC_ + 2 * group]);
            float2 v0 = make_float2(vv.x, vv.y), v1 = make_float2(vv.z, vv.w);
#pragma unroll
            for (int jb = 0; jb < JB; jb++) {
                float4 wv = sW[k * H + jj * JB + jb];
                float2 w0 = make_float2(wv.x, wv.x), w1 = make_float2(wv.y, wv.y);
                float2 w2 = make_float2(wv.z, wv.z), w3 = make_float2(wv.w, wv.w);
                acc[0][jb][0] = ffma2(w0, v0, acc[0][jb][0]);
                acc[1][jb][0] = ffma2(w1, v0, acc[1][jb][0]);
                acc[2][jb][0] = ffma2(w2, v0, acc[2][jb][0]);
                acc[3][jb][0] = ffma2(w3, v0, acc[3][jb][0]);
                acc[0][jb][1] = ffma2(w0, v1, acc[0][jb][1]);
                acc[1][jb][1] = ffma2(w1, v1, acc[1][jb][1]);
                acc[2][jb][1] = ffma2(w2, v1, acc[2][jb][1]);
                acc[3][jb][1] = ffma2(w3, v1, acc[3][jb][1]);
            }
        }

        // --- P2: poll + x loads + commit ---
        if (!FIRST) { const unsigned* f = fin + t; while (ld_acq(f) == 0) { } }
        const float* bin = bufin + (size_t)t * 16 * BATCH + b0;
        float4 pf[NLD];
#pragma unroll
        for (int L = 0; L < NLD; L++) {
            int i = wtid + L * NTHR;
            if (NQ % NTHR == 0 || i < NQ) {
                int m = i / QROW, q4 = i % QROW;
                pf[L] = __ldcg(reinterpret_cast<const float4*>(&bin[m * BATCH + 4 * q4]));
            }
        }
#pragma unroll
        for (int L = 0; L < NLD; L++) {
            int i = wtid + L * NTHR;
            if (NQ % NTHR == 0 || i < NQ) {
                int m = i / QROW, q4 = i % QROW;
                float4 v = pf[L];
                if (RELU) {
                    v.x = fmaxf(v.x, 0.f); v.y = fmaxf(v.y, 0.f);
                    v.z = fmaxf(v.z, 0.f); v.w = fmaxf(v.w, 0.f);
                }
                *reinterpret_cast<float4*>(&rows[m * BPC_ + 2 * q4]) = v;
            }
        }
        wg_bar(barid, NTHR);   // x(t) visible; all P1 h-reads complete

        // --- P3: pack0 x half ---
#pragma unroll 4
        for (int k = 0; k < DSTAGE; k++) {
            float4 vv = *reinterpret_cast<const float4*>(&rows[k * BPC_ + 2 * group]);
            float2 v0 = make_float2(vv.x, vv.y), v1 = make_float2(vv.z, vv.w);
#pragma unroll
            for (int jb = 0; jb < JB; jb++) {
                float4 wv = sW[k * H + jj * JB + jb];
                float2 w0 = make_float2(wv.x, wv.x), w1 = make_float2(wv.y, wv.y);
                float2 w2 = make_float2(wv.z, wv.z), w3 = make_float2(wv.w, wv.w);
                acc[0][jb][0] = ffma2(w0, v0, acc[0][jb][0]);
                acc[1][jb][0] = ffma2(w1, v0, acc[1][jb][0]);
                acc[2][jb][0] = ffma2(w2, v0, acc[2][jb][0]);
                acc[3][jb][0] = ffma2(w3, v0, acc[3][jb][0]);
                acc[0][jb][1] = ffma2(w0, v1, acc[0][jb][1]);
                acc[1][jb][1] = ffma2(w1, v1, acc[1][jb][1]);
                acc[2][jb][1] = ffma2(w2, v1, acc[2][jb][1]);
                acc[3][jb][1] = ffma2(w3, v1, acc[3][jb][1]);
            }
        }
        // --- pack0 activations + h0 write ---
        float* bout = bufout + (size_t)t * 16 * BATCH + b0;
#pragma unroll
        for (int jb = 0; jb < JB; jb++) {
            float2 h0 , h1;
            h0.x = cell_one(acc[0][jb][0].x, acc[1][jb][0].x, acc[2][jb][0].x,
                            acc[3][jb][0].x, c[0][jb][0].x);
            h0.y = cell_one(acc[0][jb][0].y, acc[1][jb][0].y, acc[2][jb][0].y,
                            acc[3][jb][0].y, c[0][jb][0].y);
            h1.x = cell_one(acc[0][jb][1].x, acc[1][jb][1].x, acc[2][jb][1].x,
                            acc[3][jb][1].x, c[0][jb][1].x);
            h1.y = cell_one(acc[0][jb][1].y, acc[1][jb][1].y, acc[2][jb][1].y,
                            acc[3][jb][1].y, c[0][jb][1].y);
            int j = jj * JB + jb;
            float4 hv = make_float4(h0.x, h0.y, h1.x, h1.y);
            *reinterpret_cast<float4*>(&rows[(H)*BPC_ + j * BPC_ + 2 * group]) = hv;
            if (PACK == 1)
                *reinterpret_cast<float4*>(&bout[j * BATCH + 4 * group]) = hv;
        }

        if (PACK > 1) {
            wg_bar(barid, NTHR);   // h0(t) visible
            float2 acc1[4][JB][NB];
#pragma unroll
            for (int jb = 0; jb < JB; jb++) {
                float4 bv = sB[H + jj * JB + jb];
#pragma unroll
                for (int n = 0; n < NB; n++) {
                    acc1[0][jb][n] = make_float2(bv.x, bv.x);
                    acc1[1][jb][n] = make_float2(bv.y, bv.y);
                    acc1[2][jb][n] = make_float2(bv.z, bv.z);
                    acc1[3][jb][n] = make_float2(bv.w, bv.w);
                }
            }
#pragma unroll 4
            for (int k = 0; k < KM; k++) {
                float4 vv = *reinterpret_cast<const float4*>(&rows[(H + k) * BPC_ + 2 * group]);
                float2 v0 = make_float2(vv.x, vv.y), v1 = make_float2(vv.z, vv.w);
#pragma unroll
                for (int jb = 0; jb < JB; jb++) {
                    float4 wv = sW[KM * H + k * H + jj * JB + jb];
                    float2 w0 = make_float2(wv.x, wv.x), w1 = make_float2(wv.y, wv.y);
                    float2 w2 = make_float2(wv.z, wv.z), w3 = make_float2(wv.w, wv.w);
                    acc1[0][jb][0] = ffma2(w0, v0, acc1[0][jb][0]);
                    acc1[1][jb][0] = ffma2(w1, v0, acc1[1][jb][0]);
                    acc1[2][jb][0] = ffma2(w2, v0, acc1[2][jb][0]);
                    acc1[3][jb][0] = ffma2(w3, v0, acc1[3][jb][0]);
                    acc1[0][jb][1] = ffma2(w0, v1, acc1[0][jb][1]);
                    acc1[1][jb][1] = ffma2(w1, v1, acc1[1][jb][1]);
                    acc1[2][jb][1] = ffma2(w2, v1, acc1[2][jb][1]);
                    acc1[3][jb][1] = ffma2(w3, v1, acc1[3][jb][1]);
                }
            }
            float4 hv[JB];
#pragma unroll
            for (int jb = 0; jb < JB; jb++) {
                float2 h0, h1;
                h0.x = cell_one(acc1[0][jb][0].x, acc1[1][jb][0].x, acc1[2][jb][0].x,
                                acc1[3][jb][0].x, c[1][jb][0].x);
                h0.y = cell_one(acc1[0][jb][0].y, acc1[1][jb][0].y, acc1[2][jb][0].y,
                                acc1[3][jb][0].y, c[1][jb][0].y);
                h1.x = cell_one(acc1[0][jb][1].x, acc1[1][jb][1].x, acc1[2][jb][1].x,
                                acc1[3][jb][1].x, c[1][jb][1].x);
                h1.y = cell_one(acc1[0][jb][1].y, acc1[1][jb][1].y, acc1[2][jb][1].y,
                                acc1[3][jb][1].y, c[1][jb][1].y);
                hv[jb] = make_float4(h0.x, h0.y, h1.x, h1.y);
            }
            wg_bar(barid, NTHR);   // all pack1 reads done
#pragma unroll
            for (int jb = 0; jb < JB; jb++) {
                int j = jj * JB + jb;
                *reinterpret_cast<float4*>(&rows[2 * H * BPC_ + j * BPC_ + 2 * group]) = hv[jb];
                *reinterpret_cast<float4*>(&bout[j * BATCH + 4 * group]) = hv[jb];
            }
        }

        wg_bar(barid, NTHR);   // h(t) + gout visible
        if (!LAST && wtid == 0) st_rel(fout + t, 1u);
    }
}

// ---------------------------------------------------------------------------
// 144 CTAs x 384 threads, one per SM:
//  CTA 0..127:  tid<256: s3 layer cta>>1, batch half cta&1 (BPC=64, JB=2)
//               tid>=256: s2 layer cta>>1, batch half cta&1 (BPC=64, JB=2)
//  CTA 128..143: tid<256: s1 pack2 unit cta-128, full batch (JB=1); else exit
// ---------------------------------------------------------------------------
__global__ void __launch_bounds__(384, 1)
lstm_pipe(const float* l1_Wih0, const float* l1_Whh0, const float* l1_bih0, const float* l1_bhh0,
          const float* l1_Wih,  const float* l1_Whh,  const float* l1_bih,  const float* l1_bhh,
          const float* l2_Wih0, const float* l2_Whh0, const float* l2_bih0, const float* l2_bhh0,
          const float* l2_Wih,  const float* l2_Whh,  const float* l2_bih,  const float* l2_bhh,
          const float* l3_Wih0, const float* l3_Whh0, const float* l3_bih0, const float* l3_bhh0,
          const float* l3_Wih,  const float* l3_Whh,  const float* l3_bih,  const float* l3_bhh)
{
    __shared__ __align__(16) float4 sW0[32 * 16];        // 8KB  s3 weights
    __shared__ __align__(16) float4 sB0[16];
    __shared__ __align__(16) float2 rows0[2 * 16 * 64];  // 16KB s3 rows
    __shared__ __align__(16) float4 sW1[128];            // 2KB  s2 / s1-pack2
    __shared__ __align__(16) float4 sB1[16];
    __shared__ __align__(16) float2 rows1[2048];         // 16KB

    const int tid = threadIdx.x, cta = blockIdx.x;

    if (cta < 128) {
        const int d = cta >> 1;
        if (tid < 256) {
            fill_s4<16, 8>(sW0, sB0, l3_Wih0, l3_Whh0, l3_bih0, l3_bhh0,
                           l3_Wih, l3_Whh, l3_bih, l3_bhh, d, tid, 256);
        } else {
            fill_s4<8, 4>(sW1, sB1, l2_Wih0, l2_Whh0, l2_bih0, l2_bhh0,
                          l2_Wih, l2_Whh, l2_bih, l2_bhh, d, tid - 256, 128);
        }
    } else if (tid < 256) {
        const int i0 = cta - 128;
        fill_s4<4, 2>(sW1, sB1, l1_Wih0, l1_Whh0, l1_bih0, l1_bhh0,
                      l1_Wih, l1_Whh, l1_bih, l1_bhh, 2 * i0, tid, 256);
        fill_s4<4, 2>(sW1 + 32, sB1 + 4, l1_Wih0, l1_Whh0, l1_bih0, l1_bhh0,
                      l1_Wih, l1_Whh, l1_bih, l1_bhh, 2 * i0 + 1, tid, 256);
    }
    __syncthreads();

    if (cta < 128) {
        const int d = cta >> 1, s = cta & 1;
        const int b0 = s * 128;
        if (tid < 256) {
            // ---- s3 half-batch, 256 threads, JB=2, barid 1 ----
            const int q = 80 + d;
            const float* bufin = g_act[q & 1];
            float* bufout = g_act[(q + 1) & 1];
            const unsigned* fin = (d == 0) ? FLAG(79, s) : FLAG(q - 1, s);
            unsigned* fout = FLAG(q, s);
            if (d == 0)
                stage_loop<16, 2, 1, 64, 8, 256, false, true, false>(sW0, sB0, rows0, bufin, bufout, fin, fout, b0, tid, 1);
            else if (d == 63)
                stage_loop<16, 2, 1, 64, 16, 256, false, false, true>(sW0, sB0, rows0, bufin, bufout, fin, fout, b0, tid, 1);
            else
                stage_loop<16, 2, 1, 64, 16, 256, false, false, false>(sW0, sB0, rows0, bufin, bufout, fin, fout, b0, tid, 1);
        } else {
            // ---- s2 half-batch, 128 threads, JB=2, barid 2 ----
            const int wtid = tid - 256;
            const int q = 16 + d;
            const float* bufin = g_act[q & 1];
            float* bufout = g_act[(q + 1) & 1];
            const unsigned* fin = (d == 0) ? FLAG(15, 0) : FLAG(q - 1, s);
            unsigned* fout = FLAG(q, s);
            if (d == 0)
                stage_loop<8, 2, 1, 64, 4, 128, false, true, false>(sW1, sB1, rows1, bufin, bufout, fin, fout, b0, wtid, 2);
            else
                stage_loop<8, 2, 1, 64, 8, 128, false, false, false>(sW1, sB1, rows1, bufin, bufout, fin, fout, b0, wtid, 2);
        }
    } else if (tid < 256) {
        // ---- s1 pack2, full batch, 256 threads, JB=1, barid 1 ----
        const int i0 = cta - 128, q = i0;
        const float* bufin = g_act[q & 1];
        float* bufout = g_act[(q + 1) & 1];
        const unsigned* fin = FLAG(q > 0 ? q - 1 : 0, 0);
        unsigned* fout = FLAG(q, 0);
        if (i0 == 0)
            stage_loop<4, 1, 2, 128, 2, 256, true, false, false>(sW1, sB1, rows1, bufin, bufout, fin, fout, 0, tid, 1);
        else
            stage_loop<4, 1, 2, 128, 4, 256, false, false, false>(sW1, sB1, rows1, bufin, bufout, fin, fout, 0, tid, 1);
    }
}

// ---------------------------------------------------------------------------
// Pre: transpose x -> g_act[0][t][m][b] AND clear all flags (replay-safe).
// Post: ReLU + FC(16->4).
// ---------------------------------------------------------------------------
__global__ void pre_kernel(const float* __restrict__ x) {
    int t = blockIdx.x, b = threadIdx.x;
    float2 v = *reinterpret_cast<const float2*>(&x[((size_t)t * BATCH + b) * 2]);
    g_act[0][(t * 16 + 0) * BATCH + b] = v.x;
    g_act[0][(t * 16 + 1) * BATCH + b] = v.y;
    int idx = t * BATCH + b;
    for (int i = idx; i < NSTAGES * 2 * T_STEPS; i += T_STEPS * BATCH)
        g_flags[i] = 0;
}

__global__ void fc_kernel(const float* __restrict__ fcW, const float* __restrict__ fcb,
                          float* __restrict__ out) {
    int t = blockIdx.x, b = threadIdx.x;
    float v[16];
#pragma unroll
    for (int m = 0; m < 16; m++)
        v[m] = fmaxf(g_act[0][(t * 16 + m) * BATCH + b], 0.f);
#pragma unroll
    for (int q = 0; q < 4; q++) {
        float a = fcb[q];
#pragma unroll
        for (int m = 0; m < 16; m++) a = fmaf(v[m], fcW[q * 16 + m], a);
        out[((size_t)t * BATCH + b) * 4 + q] = a;
    }
}

// ---------------------------------------------------------------------------
extern "C" void kernel_launch(void* const* d_in, const int* in_sizes, int n_in,
                              void* d_out, int out_size) {
#define F(i) ((const float*)d_in[i])
    pre_kernel<<<T_STEPS, BATCH>>>(F(0));
    lstm_pipe<<<144, 384>>>(
        F(1), F(2), F(3), F(4), F(5), F(6), F(7), F(8),
        F(9), F(10), F(11), F(12), F(13), F(14), F(15), F(16),
        F(17), F(18), F(19), F(20), F(21), F(22), F(23), F(24));
    fc_kernel<<<T_STEPS, BATCH>>>(F(25), F(26), (float*)d_out);
#undef F
}